// round 1
// baseline (speedup 1.0000x reference)
#include <cuda_runtime.h>
#include <math.h>

#define TT    2048
#define NB    8
#define NC    128
#define NCOND 16
#define NL    10

// Scratch (device globals — allocation-free per harness rules)
__device__ float g_h   [NB*TT*NC];          //  8.4 MB
__device__ float g_g   [NB*TT*NC];          //  8.4 MB
__device__ float g_skip[NB*TT*NC];          //  8.4 MB
__device__ float g_out1[NB*TT*2048];        // 134 MB
__device__ float g_out2[NB*TT*256];         // 16.8 MB

typedef unsigned long long u64;

__device__ __forceinline__ u64 pack2(float lo, float hi) {
    u64 r; asm("mov.b64 %0, {%1,%2};" : "=l"(r) : "f"(lo), "f"(hi)); return r;
}
__device__ __forceinline__ void unpack2(u64 v, float &lo, float &hi) {
    asm("mov.b64 {%0,%1}, %2;" : "=f"(lo), "=f"(hi) : "l"(v));
}
// packed dual fp32 FMA: d.lo += a.lo*b.lo ; d.hi += a.hi*b.hi
__device__ __forceinline__ void ffma2(u64 &d, u64 a, u64 b) {
    asm("fma.rn.f32x2 %0, %1, %2, %0;" : "+l"(d) : "l"(a), "l"(b));
}

// ---------------------------------------------------------------------------
// h = x * Wc + bc ;  skip_sum = 0
// ---------------------------------------------------------------------------
__global__ __launch_bounds__(256) void k_init(const float* __restrict__ x,
                                              const float* __restrict__ Wc,
                                              const float* __restrict__ bc) {
    int idx = blockIdx.x * 256 + threadIdx.x;       // over B*T*C
    int c  = idx & (NC - 1);
    int bt = idx >> 7;
    g_h[idx]    = x[bt] * Wc[c] + bc[c];
    g_skip[idx] = 0.f;
}

// ---------------------------------------------------------------------------
// Gated dilated conv + conditioning:
//   g = tanh(convT(h) + bt + cond@Dt + Bt) * sigmoid(convS(h) + bs + cond@Ds + Bs)
// CTA: 4 t-positions x 4 batches x all 128 co. threads = co.
// smem: 3 shifted h-tiles transposed to [tap][ci][row] for broadcast LDS.64.
// ---------------------------------------------------------------------------
__global__ __launch_bounds__(128) void k_gated(
    const float* __restrict__ Wt, const float* __restrict__ btb,
    const float* __restrict__ Ws, const float* __restrict__ bsb,
    const float* __restrict__ Dt, const float* __restrict__ Btb,
    const float* __restrict__ Ds, const float* __restrict__ Bsb,
    const float* __restrict__ cond, int l, int d)
{
    const int t0 = blockIdx.x * 4;
    const int bh = blockIdx.y * 4;          // batch base (0 or 4)
    const int co = threadIdx.x;

    __shared__ float sh[3][NC][18];         // rows: r = b_local*4 + t (16 used)
    __shared__ float scond[4][NCOND];

    if (co < 64) scond[co >> 4][co & 15] = cond[(bh + (co >> 4)) * NCOND + (co & 15)];

    #pragma unroll
    for (int k = 0; k < 3; k++) {
        int tb = t0 + (k - 1) * d;
        #pragma unroll
        for (int r = 0; r < 16; r++) {
            int b = bh + (r >> 2);
            int t = tb + (r & 3);
            float v = 0.f;
            if ((unsigned)t < TT) v = g_h[(b * TT + t) * NC + co];
            sh[k][co][r] = v;
        }
    }
    __syncthreads();

    // accumulators initialized with conditioning term (Bt + bt + cond @ Dt)
    float atf[16], asf[16];
    float btv = btb[l * NC + co], bsv = bsb[l * NC + co];
    #pragma unroll
    for (int t = 0; t < 4; t++) {
        size_t bo = ((size_t)l * TT + (t0 + t)) * NC + co;
        float vt = Btb[bo] + btv;
        float vs = Bsb[bo] + bsv;
        #pragma unroll
        for (int b = 0; b < 4; b++) { atf[b*4+t] = vt; asf[b*4+t] = vs; }
    }
    #pragma unroll 4
    for (int c = 0; c < NCOND; c++) {
        #pragma unroll
        for (int t = 0; t < 4; t++) {
            size_t off = (((size_t)l * NCOND + c) * TT + (t0 + t)) * NC + co;
            float dtv = Dt[off], dsv = Ds[off];
            #pragma unroll
            for (int b = 0; b < 4; b++) {
                atf[b*4+t] = fmaf(scond[b][c], dtv, atf[b*4+t]);
                asf[b*4+t] = fmaf(scond[b][c], dsv, asf[b*4+t]);
            }
        }
    }
    u64 at[8], as2[8];
    #pragma unroll
    for (int i = 0; i < 8; i++) {
        at[i]  = pack2(atf[2*i], atf[2*i+1]);
        as2[i] = pack2(asf[2*i], asf[2*i+1]);
    }

    // conv: per (k,ci): 2 LDG + 2 pack + 8 LDS.64 + 16 FFMA2 (32 MACs)
    const float* wtp = Wt + (size_t)l * 3 * NC * NC + co;
    const float* wsp = Ws + (size_t)l * 3 * NC * NC + co;
    #pragma unroll 1
    for (int k = 0; k < 3; k++) {
        #pragma unroll 2
        for (int ci = 0; ci < NC; ci++) {
            float wt = wtp[(k * NC + ci) * NC];
            float ws = wsp[(k * NC + ci) * NC];
            u64 wt2 = pack2(wt, wt);
            u64 ws2 = pack2(ws, ws);
            const u64* hp = (const u64*)(&sh[k][ci][0]);
            #pragma unroll
            for (int b = 0; b < 4; b++) {
                u64 h01 = hp[b*2], h23 = hp[b*2 + 1];
                ffma2(at[b*2],   h01, wt2);
                ffma2(at[b*2+1], h23, wt2);
                ffma2(as2[b*2],   h01, ws2);
                ffma2(as2[b*2+1], h23, ws2);
            }
        }
    }

    #pragma unroll
    for (int b = 0; b < 4; b++) {
        #pragma unroll
        for (int p = 0; p < 2; p++) {
            float x0, x1, s0, s1;
            unpack2(at[b*2+p],  x0, x1);
            unpack2(as2[b*2+p], s0, s1);
            int t = t0 + p * 2;
            float g0 = tanhf(x0) / (1.f + expf(-s0));
            float g1 = tanhf(x1) / (1.f + expf(-s1));
            g_g[((bh + b) * TT + t)     * NC + co] = g0;
            g_g[((bh + b) * TT + t + 1) * NC + co] = g1;
        }
    }
}

// ---------------------------------------------------------------------------
// skip_sum += g @ Wskip + bskip ;  h = g @ Wres + bres + h   (1x1 convs)
// CTA: 32 flattened (b,t) rows x all 128 co.
// ---------------------------------------------------------------------------
__global__ __launch_bounds__(128) void k_post(
    const float* __restrict__ Wskip, const float* __restrict__ bskip,
    const float* __restrict__ Wres,  const float* __restrict__ bres, int l)
{
    const int R0 = blockIdx.x * 32;
    const int co = threadIdx.x;
    __shared__ float sg[NC][34];

    #pragma unroll
    for (int r = 0; r < 32; r++) sg[co][r] = g_g[(R0 + r) * NC + co];
    __syncthreads();

    u64 ak[16], ar[16];
    #pragma unroll
    for (int i = 0; i < 16; i++) { ak[i] = 0ull; ar[i] = 0ull; }

    const float* wkp = Wskip + (size_t)l * NC * NC + co;
    const float* wrp = Wres  + (size_t)l * NC * NC + co;
    #pragma unroll 2
    for (int ci = 0; ci < NC; ci++) {
        float wk = wkp[ci * NC];
        float wr = wrp[ci * NC];
        u64 wk2 = pack2(wk, wk), wr2 = pack2(wr, wr);
        const u64* gp = (const u64*)(&sg[ci][0]);
        #pragma unroll
        for (int p = 0; p < 16; p++) {
            u64 gv = gp[p];
            ffma2(ak[p], gv, wk2);
            ffma2(ar[p], gv, wr2);
        }
    }
    float bk = bskip[l * NC + co], br = bres[l * NC + co];
    #pragma unroll
    for (int p = 0; p < 16; p++) {
        float k0, k1, r0, r1;
        unpack2(ak[p], k0, k1);
        unpack2(ar[p], r0, r1);
        int i0 = (R0 + 2 * p) * NC + co;
        int i1 = i0 + NC;
        g_skip[i0] += k0 + bk;
        g_skip[i1] += k1 + bk;
        g_h[i0]    += r0 + br;
        g_h[i1]    += r1 + br;
    }
}

// ---------------------------------------------------------------------------
// out1 = relu(conv3(skip, W1) + b1)   [B,T,2048]
// CTA: 16 t x 512 co (thread handles 4 co), one batch.
// ---------------------------------------------------------------------------
__global__ __launch_bounds__(128) void k_head1(const float* __restrict__ W1,
                                               const float* __restrict__ b1)
{
    const int t0 = blockIdx.x * 16;
    const int b  = blockIdx.y;
    const int cz = blockIdx.z * 512;
    const int tid = threadIdx.x;
    __shared__ float s1[3][NC][18];

    #pragma unroll
    for (int k = 0; k < 3; k++) {
        #pragma unroll
        for (int t = 0; t < 16; t++) {
            int ti = t0 + t + k - 1;
            float v = 0.f;
            if ((unsigned)ti < TT) v = g_skip[(b * TT + ti) * NC + tid];
            s1[k][tid][t] = v;
        }
    }
    __syncthreads();

    u64 acc[8][4];
    #pragma unroll
    for (int p = 0; p < 8; p++)
        #pragma unroll
        for (int j = 0; j < 4; j++) acc[p][j] = 0ull;

    #pragma unroll 1
    for (int k = 0; k < 3; k++) {
        #pragma unroll 2
        for (int ci = 0; ci < NC; ci++) {
            const float* wp = W1 + ((size_t)(k * NC + ci)) * 2048 + cz + tid;
            u64 w2[4];
            #pragma unroll
            for (int j = 0; j < 4; j++) { float w = wp[128 * j]; w2[j] = pack2(w, w); }
            const u64* hp = (const u64*)(&s1[k][ci][0]);
            #pragma unroll
            for (int p = 0; p < 8; p++) {
                u64 h2 = hp[p];
                #pragma unroll
                for (int j = 0; j < 4; j++) ffma2(acc[p][j], h2, w2[j]);
            }
        }
    }
    #pragma unroll
    for (int j = 0; j < 4; j++) {
        int cg = cz + tid + 128 * j;
        float bb = b1[cg];
        #pragma unroll
        for (int p = 0; p < 8; p++) {
            float v0, v1; unpack2(acc[p][j], v0, v1);
            v0 = fmaxf(v0 + bb, 0.f);
            v1 = fmaxf(v1 + bb, 0.f);
            g_out1[((size_t)(b * TT + t0 + 2 * p))     * 2048 + cg] = v0;
            g_out1[((size_t)(b * TT + t0 + 2 * p + 1)) * 2048 + cg] = v1;
        }
    }
}

// ---------------------------------------------------------------------------
// out2 = relu(conv3(out1, W2) + b2)   [B,T,256]
// CTA: 16 t x 256 co (thread handles 2 co); K = 3x2048 streamed in 128-ci chunks.
// ---------------------------------------------------------------------------
__global__ __launch_bounds__(128) void k_head2(const float* __restrict__ W2,
                                               const float* __restrict__ b2)
{
    const int t0 = blockIdx.x * 16;
    const int b  = blockIdx.y;
    const int tid = threadIdx.x;
    __shared__ float s2[3][NC][18];

    u64 acc[8][2];
    #pragma unroll
    for (int p = 0; p < 8; p++) { acc[p][0] = 0ull; acc[p][1] = 0ull; }

    #pragma unroll 1
    for (int cc = 0; cc < 16; cc++) {
        __syncthreads();
        #pragma unroll
        for (int k = 0; k < 3; k++) {
            #pragma unroll
            for (int t = 0; t < 16; t++) {
                int ti = t0 + t + k - 1;
                float v = 0.f;
                if ((unsigned)ti < TT)
                    v = g_out1[((size_t)(b * TT + ti)) * 2048 + cc * 128 + tid];
                s2[k][tid][t] = v;
            }
        }
        __syncthreads();
        #pragma unroll 1
        for (int k = 0; k < 3; k++) {
            #pragma unroll 2
            for (int ci = 0; ci < NC; ci++) {
                const float* wp = W2 + ((size_t)(k * 2048 + cc * 128 + ci)) * 256 + tid;
                float wa = wp[0], wb = wp[128];
                u64 w2a = pack2(wa, wa), w2b = pack2(wb, wb);
                const u64* hp = (const u64*)(&s2[k][ci][0]);
                #pragma unroll
                for (int p = 0; p < 8; p++) {
                    u64 h2 = hp[p];
                    ffma2(acc[p][0], h2, w2a);
                    ffma2(acc[p][1], h2, w2b);
                }
            }
        }
    }
    #pragma unroll
    for (int j = 0; j < 2; j++) {
        float bb = b2[tid + 128 * j];
        #pragma unroll
        for (int p = 0; p < 8; p++) {
            float v0, v1; unpack2(acc[p][j], v0, v1);
            v0 = fmaxf(v0 + bb, 0.f);
            v1 = fmaxf(v1 + bb, 0.f);
            g_out2[(b * TT + t0 + 2 * p)     * 256 + tid + 128 * j] = v0;
            g_out2[(b * TT + t0 + 2 * p + 1) * 256 + tid + 128 * j] = v1;
        }
    }
}

// ---------------------------------------------------------------------------
// out = tanh(out2 @ W3 + b3)   [B,T,1]  — one warp per row
// ---------------------------------------------------------------------------
__global__ __launch_bounds__(128) void k_head3(const float* __restrict__ W3,
                                               const float* __restrict__ b3,
                                               float* __restrict__ out)
{
    int row  = blockIdx.x * 4 + (threadIdx.x >> 5);
    int lane = threadIdx.x & 31;
    const float* p = g_out2 + (size_t)row * 256;
    float s = 0.f;
    #pragma unroll
    for (int i = 0; i < 8; i++) s = fmaf(p[lane + 32 * i], W3[lane + 32 * i], s);
    #pragma unroll
    for (int o = 16; o; o >>= 1) s += __shfl_xor_sync(0xffffffffu, s, o);
    if (lane == 0) out[row] = tanhf(s + b3[0]);
}

// ---------------------------------------------------------------------------
extern "C" void kernel_launch(void* const* d_in, const int* in_sizes, int n_in,
                              void* d_out, int out_size) {
    const float* x     = (const float*)d_in[0];
    const float* cond  = (const float*)d_in[1];
    const float* Wc    = (const float*)d_in[2];
    const float* bc    = (const float*)d_in[3];
    const float* Wt    = (const float*)d_in[4];
    const float* bt    = (const float*)d_in[5];
    const float* Ws    = (const float*)d_in[6];
    const float* bs    = (const float*)d_in[7];
    const float* Dt    = (const float*)d_in[8];
    const float* Bt    = (const float*)d_in[9];
    const float* Ds    = (const float*)d_in[10];
    const float* Bs    = (const float*)d_in[11];
    const float* Wskip = (const float*)d_in[12];
    const float* bskip = (const float*)d_in[13];
    const float* Wres  = (const float*)d_in[14];
    const float* bres  = (const float*)d_in[15];
    const float* W1    = (const float*)d_in[16];
    const float* b1    = (const float*)d_in[17];
    const float* W2    = (const float*)d_in[18];
    const float* b2    = (const float*)d_in[19];
    const float* W3    = (const float*)d_in[20];
    const float* b3    = (const float*)d_in[21];
    float* out = (float*)d_out;

    k_init<<<NB * TT * NC / 256, 256>>>(x, Wc, bc);

    const int dil[NL] = {1, 2, 4, 8, 16, 32, 64, 128, 256, 512};
    for (int l = 0; l < NL; l++) {
        k_gated<<<dim3(TT / 4, 2), 128>>>(Wt, bt, Ws, bs, Dt, Bt, Ds, Bs, cond, l, dil[l]);
        k_post<<<NB * TT / 32, 128>>>(Wskip, bskip, Wres, bres, l);
    }
    k_head1<<<dim3(TT / 16, NB, 4), 128>>>(W1, b1);
    k_head2<<<dim3(TT / 16, NB), 128>>>(W2, b2);
    k_head3<<<NB * TT / 4, 128>>>(W3, b3, out);
}

// round 3
// speedup vs baseline: 1.5462x; 1.5462x over previous
#include <cuda_runtime.h>
#include <cuda_bf16.h>
#include <math.h>
#include <stdint.h>

#define TT    2048
#define NB    8
#define NC    128
#define NCOND 16
#define NL    10

// tcgen05 only exists in the arch-specific (sm_10xa) compile passes.
#if defined(__CUDA_ARCH_FEAT_SM103_ALL) || defined(__CUDA_ARCH_FEAT_SM100_ALL) || defined(__CUDA_ARCH_FEAT_SM101_ALL)
#define HAS_TCGEN05 1
#else
#define HAS_TCGEN05 0
#endif

typedef unsigned long long u64;

// ---------------------------------------------------------------------------
// Device scratch (allocation-free)
// ---------------------------------------------------------------------------
__device__ float g_h   [NB*TT*NC];
__device__ float g_g   [NB*TT*NC];
__device__ float g_skip[NB*TT*NC];
__device__ float g_out2[NB*TT*256];

__device__ __nv_bfloat16 g_skipHi[NB*TT*NC];
__device__ __nv_bfloat16 g_skipLo[NB*TT*NC];
__device__ __nv_bfloat16 g_W1tHi [3*2048*128];   // [tap][co][ci]
__device__ __nv_bfloat16 g_W1tLo [3*2048*128];
__device__ __nv_bfloat16 g_W2tHi [3*256*2048];   // [tap][co][ci]
__device__ __nv_bfloat16 g_W2tLo [3*256*2048];
__device__ __nv_bfloat16 g_out1Hi[(size_t)NB*TT*2048];
__device__ __nv_bfloat16 g_out1Lo[(size_t)NB*TT*2048];

// ---------------------------------------------------------------------------
// helpers
// ---------------------------------------------------------------------------
__device__ __forceinline__ uint32_t smem_to_u32(const void* p) {
    uint32_t a;
    asm("{ .reg .u64 t; cvta.to.shared.u64 t, %1; cvt.u32.u64 %0, t; }"
        : "=r"(a) : "l"(p));
    return a;
}
__device__ __forceinline__ u64 pack2(float lo, float hi) {
    u64 r; asm("mov.b64 %0, {%1,%2};" : "=l"(r) : "f"(lo), "f"(hi)); return r;
}
__device__ __forceinline__ void unpack2(u64 v, float &lo, float &hi) {
    asm("mov.b64 {%0,%1}, %2;" : "=f"(lo), "=f"(hi) : "l"(v));
}
__device__ __forceinline__ void ffma2(u64 &d, u64 a, u64 b) {
    asm("fma.rn.f32x2 %0, %1, %2, %0;" : "+l"(d) : "l"(a), "l"(b));
}

#if HAS_TCGEN05
__device__ __forceinline__ uint32_t elect_one_pred() {
    uint32_t pred;
    asm volatile(
        "{\n\t.reg .pred p;\n\telect.sync _|p, 0xFFFFFFFF;\n\t"
        "selp.b32 %0, 1, 0, p;\n\t}" : "=r"(pred));
    return pred;
}

#define TCGEN05_ALLOC(smem_result_addr, nCols) \
    asm volatile("tcgen05.alloc.cta_group::1.sync.aligned.shared::cta.b32 [%0], %1;" \
        :: "r"((uint32_t)(smem_result_addr)), "r"((uint32_t)(nCols)) : "memory")
#define TCGEN05_DEALLOC(tmem_addr, nCols) \
    asm volatile("tcgen05.dealloc.cta_group::1.sync.aligned.b32 %0, %1;" \
        :: "r"(tmem_addr), "r"((uint32_t)(nCols)))
#define TCGEN05_RELINQUISH_ALLOC_PERMIT() \
    asm volatile("tcgen05.relinquish_alloc_permit.cta_group::1.sync.aligned;")
#define TCGEN05_COMMIT(mbar_smem_addr) \
    asm volatile("tcgen05.commit.cta_group::1.mbarrier::arrive::one.shared::cluster.b64 [%0];" \
        :: "r"((uint32_t)(mbar_smem_addr)) : "memory")
#define TCGEN05_FENCE_AFTER() \
    asm volatile("tcgen05.fence::after_thread_sync;" ::: "memory")
#define TCGEN05_WAIT_LD() \
    asm volatile("tcgen05.wait::ld.sync.aligned;" ::: "memory")
#define FENCE_PROXY_ASYNC_SHARED_CTA() \
    asm volatile("fence.proxy.async.shared::cta;" ::: "memory")
#define MBARRIER_INIT(mbar_smem_addr, count) \
    asm volatile("mbarrier.init.shared.b64 [%0], %1;" \
        :: "r"((uint32_t)(mbar_smem_addr)), "r"((uint32_t)(count)) : "memory")

#define MBARRIER_WAIT_PARITY(mbar_smem_addr, phase_parity) do { \
    uint32_t _mbar = (uint32_t)(mbar_smem_addr); \
    uint32_t _parity = (uint32_t)(phase_parity); \
    uint32_t _done; \
    asm volatile( \
        "{\n\t.reg .pred p;\n\t" \
        "mbarrier.try_wait.parity.acquire.cta.shared::cta.b64 p, [%1], %2;\n\t" \
        "selp.b32 %0, 1, 0, p;\n\t}" \
        : "=r"(_done) : "r"(_mbar), "r"(_parity) : "memory"); \
    if (!_done) { \
        asm volatile( \
            "{\n\t.reg .pred P1;\n\t" \
            "WAIT_LOOP_%=:\n\t" \
            "mbarrier.try_wait.parity.acquire.cta.shared::cta.b64 P1, [%0], %1, 0x989680;\n\t" \
            "@P1 bra.uni WAIT_DONE_%=;\n\t" \
            "bra.uni WAIT_LOOP_%=;\n\t" \
            "WAIT_DONE_%=:\n\t}" \
            :: "r"(_mbar), "r"(_parity) : "memory"); \
    } \
} while(0)

#define TCGEN05_LD_32X32B_X32(r, tmem_addr) \
    asm volatile( \
        "tcgen05.ld.sync.aligned.32x32b.x32.b32 " \
        "{%0, %1, %2, %3, %4, %5, %6, %7, " \
        " %8, %9, %10, %11, %12, %13, %14, %15, " \
        " %16, %17, %18, %19, %20, %21, %22, %23, " \
        " %24, %25, %26, %27, %28, %29, %30, %31}, [%32];" \
        : "=r"((r)[0]),  "=r"((r)[1]),  "=r"((r)[2]),  "=r"((r)[3]), \
          "=r"((r)[4]),  "=r"((r)[5]),  "=r"((r)[6]),  "=r"((r)[7]), \
          "=r"((r)[8]),  "=r"((r)[9]),  "=r"((r)[10]), "=r"((r)[11]), \
          "=r"((r)[12]), "=r"((r)[13]), "=r"((r)[14]), "=r"((r)[15]), \
          "=r"((r)[16]), "=r"((r)[17]), "=r"((r)[18]), "=r"((r)[19]), \
          "=r"((r)[20]), "=r"((r)[21]), "=r"((r)[22]), "=r"((r)[23]), \
          "=r"((r)[24]), "=r"((r)[25]), "=r"((r)[26]), "=r"((r)[27]), \
          "=r"((r)[28]), "=r"((r)[29]), "=r"((r)[30]), "=r"((r)[31]) \
        : "r"(tmem_addr))

static constexpr unsigned long long SMEM_DESC_BASE_SW128 =
    (2ull << 61) | (1ull << 46) | (64ull << 32) | (1ull << 16);
#define MAKE_SMEM_DESC(a) (SMEM_DESC_BASE_SW128 | ((unsigned long long)((a) >> 4) & 0x3FFF))

__device__ __forceinline__ void mma_bf16_ss(uint32_t d, u64 ad, u64 bd,
                                            uint32_t idesc, uint32_t en) {
    asm volatile(
        "{\n\t.reg .pred p;\n\t"
        "setp.ne.u32 p, %4, 0;\n\t"
        "tcgen05.mma.cta_group::1.kind::f16 [%0], %1, %2, %3, {%5, %5, %5, %5}, p;\n\t"
        "}"
        :: "r"(d), "l"(ad), "l"(bd), "r"(idesc), "r"(en), "r"(0u)
        : "memory");
}

// idesc: dtype F32(bit4), atype BF16(bit7), btype BF16(bit10), N/8<<17, M/16<<24
static constexpr uint32_t GEMM_IDESC =
    (1u << 4) | (1u << 7) | (1u << 10) | ((128u / 8) << 17) | ((128u / 16) << 24);
#endif // HAS_TCGEN05

// ---------------------------------------------------------------------------
// h = x * Wc + bc ;  skip_sum = 0
// ---------------------------------------------------------------------------
__global__ __launch_bounds__(256) void k_init(const float* __restrict__ x,
                                              const float* __restrict__ Wc,
                                              const float* __restrict__ bc) {
    int idx = blockIdx.x * 256 + threadIdx.x;
    int c  = idx & (NC - 1);
    int bt = idx >> 7;
    g_h[idx]    = x[bt] * Wc[c] + bc[c];
    g_skip[idx] = 0.f;
}

// ---------------------------------------------------------------------------
// Gated dilated conv + conditioning (FFMA2 path, unchanged)
// ---------------------------------------------------------------------------
__global__ __launch_bounds__(128) void k_gated(
    const float* __restrict__ Wt, const float* __restrict__ btb,
    const float* __restrict__ Ws, const float* __restrict__ bsb,
    const float* __restrict__ Dt, const float* __restrict__ Btb,
    const float* __restrict__ Ds, const float* __restrict__ Bsb,
    const float* __restrict__ cond, int l, int d)
{
    const int t0 = blockIdx.x * 4;
    const int bh = blockIdx.y * 4;
    const int co = threadIdx.x;

    __shared__ float sh[3][NC][18];
    __shared__ float scond[4][NCOND];

    if (co < 64) scond[co >> 4][co & 15] = cond[(bh + (co >> 4)) * NCOND + (co & 15)];

    #pragma unroll
    for (int k = 0; k < 3; k++) {
        int tb = t0 + (k - 1) * d;
        #pragma unroll
        for (int r = 0; r < 16; r++) {
            int b = bh + (r >> 2);
            int t = tb + (r & 3);
            float v = 0.f;
            if ((unsigned)t < TT) v = g_h[(b * TT + t) * NC + co];
            sh[k][co][r] = v;
        }
    }
    __syncthreads();

    float atf[16], asf[16];
    float btv = btb[l * NC + co], bsv = bsb[l * NC + co];
    #pragma unroll
    for (int t = 0; t < 4; t++) {
        size_t bo = ((size_t)l * TT + (t0 + t)) * NC + co;
        float vt = Btb[bo] + btv;
        float vs = Bsb[bo] + bsv;
        #pragma unroll
        for (int b = 0; b < 4; b++) { atf[b*4+t] = vt; asf[b*4+t] = vs; }
    }
    #pragma unroll 4
    for (int c = 0; c < NCOND; c++) {
        #pragma unroll
        for (int t = 0; t < 4; t++) {
            size_t off = (((size_t)l * NCOND + c) * TT + (t0 + t)) * NC + co;
            float dtv = Dt[off], dsv = Ds[off];
            #pragma unroll
            for (int b = 0; b < 4; b++) {
                atf[b*4+t] = fmaf(scond[b][c], dtv, atf[b*4+t]);
                asf[b*4+t] = fmaf(scond[b][c], dsv, asf[b*4+t]);
            }
        }
    }
    u64 at[8], as2[8];
    #pragma unroll
    for (int i = 0; i < 8; i++) {
        at[i]  = pack2(atf[2*i], atf[2*i+1]);
        as2[i] = pack2(asf[2*i], asf[2*i+1]);
    }

    const float* wtp = Wt + (size_t)l * 3 * NC * NC + co;
    const float* wsp = Ws + (size_t)l * 3 * NC * NC + co;
    #pragma unroll 1
    for (int k = 0; k < 3; k++) {
        #pragma unroll 2
        for (int ci = 0; ci < NC; ci++) {
            float wt = wtp[(k * NC + ci) * NC];
            float ws = wsp[(k * NC + ci) * NC];
            u64 wt2 = pack2(wt, wt);
            u64 ws2 = pack2(ws, ws);
            const u64* hp = (const u64*)(&sh[k][ci][0]);
            #pragma unroll
            for (int b = 0; b < 4; b++) {
                u64 h01 = hp[b*2], h23 = hp[b*2 + 1];
                ffma2(at[b*2],   h01, wt2);
                ffma2(at[b*2+1], h23, wt2);
                ffma2(as2[b*2],   h01, ws2);
                ffma2(as2[b*2+1], h23, ws2);
            }
        }
    }

    #pragma unroll
    for (int b = 0; b < 4; b++) {
        #pragma unroll
        for (int p = 0; p < 2; p++) {
            float x0, x1, s0, s1;
            unpack2(at[b*2+p],  x0, x1);
            unpack2(as2[b*2+p], s0, s1);
            int t = t0 + p * 2;
            float g0 = tanhf(x0) / (1.f + expf(-s0));
            float g1 = tanhf(x1) / (1.f + expf(-s1));
            g_g[((bh + b) * TT + t)     * NC + co] = g0;
            g_g[((bh + b) * TT + t + 1) * NC + co] = g1;
        }
    }
}

// ---------------------------------------------------------------------------
// skip_sum += g @ Wskip + bskip ;  h = g @ Wres + bres + h (FFMA2 path)
// ---------------------------------------------------------------------------
__global__ __launch_bounds__(128) void k_post(
    const float* __restrict__ Wskip, const float* __restrict__ bskip,
    const float* __restrict__ Wres,  const float* __restrict__ bres, int l)
{
    const int R0 = blockIdx.x * 32;
    const int co = threadIdx.x;
    __shared__ float sg[NC][34];

    #pragma unroll
    for (int r = 0; r < 32; r++) sg[co][r] = g_g[(R0 + r) * NC + co];
    __syncthreads();

    u64 ak[16], ar[16];
    #pragma unroll
    for (int i = 0; i < 16; i++) { ak[i] = 0ull; ar[i] = 0ull; }

    const float* wkp = Wskip + (size_t)l * NC * NC + co;
    const float* wrp = Wres  + (size_t)l * NC * NC + co;
    #pragma unroll 2
    for (int ci = 0; ci < NC; ci++) {
        float wk = wkp[ci * NC];
        float wr = wrp[ci * NC];
        u64 wk2 = pack2(wk, wk), wr2 = pack2(wr, wr);
        const u64* gp = (const u64*)(&sg[ci][0]);
        #pragma unroll
        for (int p = 0; p < 16; p++) {
            u64 gv = gp[p];
            ffma2(ak[p], gv, wk2);
            ffma2(ar[p], gv, wr2);
        }
    }
    float bk = bskip[l * NC + co], br = bres[l * NC + co];
    #pragma unroll
    for (int p = 0; p < 16; p++) {
        float k0, k1, r0, r1;
        unpack2(ak[p], k0, k1);
        unpack2(ar[p], r0, r1);
        int i0 = (R0 + 2 * p) * NC + co;
        int i1 = i0 + NC;
        g_skip[i0] += k0 + bk;
        g_skip[i1] += k1 + bk;
        g_h[i0]    += r0 + br;
        g_h[i1]    += r1 + br;
    }
}

// ---------------------------------------------------------------------------
// fp32 -> bf16 hi/lo split of skip_sum
// ---------------------------------------------------------------------------
__global__ __launch_bounds__(256) void k_cvtA() {
    int i = (blockIdx.x * 256 + threadIdx.x) * 4;
    float4 v = *(const float4*)(g_skip + i);
    __nv_bfloat16 h[4], l[4];
    float vv[4] = {v.x, v.y, v.z, v.w};
    #pragma unroll
    for (int j = 0; j < 4; j++) {
        h[j] = __float2bfloat16(vv[j]);
        l[j] = __float2bfloat16(vv[j] - __bfloat162float(h[j]));
    }
    *(uint2*)(g_skipHi + i) = *(const uint2*)h;
    *(uint2*)(g_skipLo + i) = *(const uint2*)l;
}

// ---------------------------------------------------------------------------
// Transpose + split head weights: src [3,K,N] fp32 -> dst [3,N,K] bf16 hi/lo
// ---------------------------------------------------------------------------
__global__ void k_cvtW(const float* __restrict__ src,
                       __nv_bfloat16* __restrict__ dhi,
                       __nv_bfloat16* __restrict__ dlo, int K, int N) {
    __shared__ float t[32][33];
    int tap = blockIdx.z;
    int n0 = blockIdx.x * 32, k0 = blockIdx.y * 32;
    int tx = threadIdx.x, ty = threadIdx.y;
    #pragma unroll
    for (int r = 0; r < 4; r++)
        t[ty + r*8][tx] = src[((size_t)tap*K + k0 + ty + r*8) * N + n0 + tx];
    __syncthreads();
    #pragma unroll
    for (int r = 0; r < 4; r++) {
        float v = t[tx][ty + r*8];
        __nv_bfloat16 h = __float2bfloat16(v);
        __nv_bfloat16 l = __float2bfloat16(v - __bfloat162float(h));
        size_t o = ((size_t)tap*N + n0 + ty + r*8) * K + k0 + tx;
        dhi[o] = h; dlo[o] = l;
    }
}

// ---------------------------------------------------------------------------
// tcgen05 GEMM-conv3 (SAME padding):
//   out[b,t,co] = relu( sum_{k,ci} A[b,t+k-1,ci] * W[k,ci,co] + bias[co] )
// A,W bf16 hi/lo split (3-term product). M-tile=128 (t, one batch), N-tile=128.
// ---------------------------------------------------------------------------
#define GEMM_SMEM (1024 + 1024 + 131072)

template<bool WB16>
__global__ __launch_bounds__(256) void k_gemm(
    const __nv_bfloat16* __restrict__ aHi, const __nv_bfloat16* __restrict__ aLo,
    const __nv_bfloat16* __restrict__ wHi, const __nv_bfloat16* __restrict__ wLo,
    const float* __restrict__ bias,
    __nv_bfloat16* __restrict__ oHi, __nv_bfloat16* __restrict__ oLo,
    float* __restrict__ oF, int Cin, int CO)
{
#if HAS_TCGEN05
    extern __shared__ char dsm[];
    const int tid = threadIdx.x;
    const int wid = tid >> 5;
    const int lane = tid & 31;

    uint32_t raw = smem_to_u32(dsm);
    uint32_t abase = (raw + 1023) & ~1023u;
    char* hdr   = dsm + (abase - raw);
    char* tiles = hdr + 1024;
    const uint32_t hdr_a   = abase;
    const uint32_t tiles_a = abase + 1024;
    float* sbias = (float*)(hdr + 512);

    const int b  = blockIdx.x >> 4;
    const int t0 = (blockIdx.x & 15) * 128;
    const int n0 = blockIdx.y * 128;

    if (tid == 0) {
        MBARRIER_INIT(hdr_a + 8, 1);
        MBARRIER_INIT(hdr_a + 16, 1);
    }
    if (wid == 0) TCGEN05_ALLOC(hdr_a, 128);
    if (tid < 128) sbias[tid] = bias[n0 + tid];
    __syncthreads();

    uint32_t tmem;
    asm volatile("ld.shared.b32 %0, [%1];" : "=r"(tmem) : "r"(hdr_a));

    const int nci = Cin >> 6;          // 64-ci chunks per tap
    const int nchunks = 3 * nci;
    const size_t aBatch = (size_t)b * TT * Cin;

    int phase[2] = {0, 0};

    for (int ch = 0; ch < nchunks; ch++) {
        const int buf = ch & 1;
        char* tb = tiles + buf * 65536;
        const uint32_t tb_a = tiles_a + buf * 65536;

        if (ch >= 2) {
            MBARRIER_WAIT_PARITY(hdr_a + 8 + 8 * buf, phase[buf]);
            phase[buf] ^= 1;
        }

        const int tap = ch / nci;
        const int ci0 = (ch - tap * nci) << 6;
        const size_t bBase = ((size_t)tap * CO + n0) * Cin + ci0;

        const int c = tid & 7;
        #pragma unroll
        for (int p = 0; p < 4; p++) {
            int r = p * 32 + (tid >> 3);
            uint32_t so = r * 128 + (((uint32_t)(c ^ (r & 7))) << 4);
            int trow = t0 + r + tap - 1;
            uint4 vah = make_uint4(0,0,0,0), val = make_uint4(0,0,0,0);
            if ((unsigned)trow < (unsigned)TT) {
                size_t off = aBatch + (size_t)trow * Cin + ci0 + c * 8;
                vah = *(const uint4*)(aHi + off);
                val = *(const uint4*)(aLo + off);
            }
            *(uint4*)(tb + so)         = vah;
            *(uint4*)(tb + 16384 + so) = val;
            size_t bo = bBase + (size_t)r * Cin + c * 8;
            *(uint4*)(tb + 32768 + so) = *(const uint4*)(wHi + bo);
            *(uint4*)(tb + 49152 + so) = *(const uint4*)(wLo + bo);
        }
        FENCE_PROXY_ASYNC_SHARED_CTA();
        __syncthreads();

        if (wid == 0 && elect_one_pred()) {
            u64 dAh = MAKE_SMEM_DESC(tb_a);
            u64 dAl = MAKE_SMEM_DESC(tb_a + 16384);
            u64 dBh = MAKE_SMEM_DESC(tb_a + 32768);
            u64 dBl = MAKE_SMEM_DESC(tb_a + 49152);
            uint32_t en = (ch != 0);
            #pragma unroll
            for (int ks = 0; ks < 4; ks++) {       // K=16 bf16 per MMA step
                mma_bf16_ss(tmem, dAh + 2*ks, dBh + 2*ks, GEMM_IDESC, en); en = 1;
                mma_bf16_ss(tmem, dAh + 2*ks, dBl + 2*ks, GEMM_IDESC, 1);
                mma_bf16_ss(tmem, dAl + 2*ks, dBh + 2*ks, GEMM_IDESC, 1);
            }
            TCGEN05_COMMIT(hdr_a + 8 + 8 * buf);
        }
    }

    MBARRIER_WAIT_PARITY(hdr_a + 8,  phase[0]);
    MBARRIER_WAIT_PARITY(hdr_a + 16, phase[1]);
    TCGEN05_FENCE_AFTER();

    const int m = (wid & 3) * 32 + lane;
    const size_t grow = (size_t)(b * TT + t0 + m);
    #pragma unroll
    for (int half = 0; half < 2; half++) {
        int col0 = (wid >> 2) * 64 + half * 32;
        uint32_t r32[32];
        TCGEN05_LD_32X32B_X32(r32, tmem + col0);
        TCGEN05_WAIT_LD();
        #pragma unroll
        for (int j0 = 0; j0 < 32; j0 += 8) {
            if (WB16) {
                __nv_bfloat16 hv[8], lv[8];
                #pragma unroll
                for (int jj = 0; jj < 8; jj++) {
                    float v = __uint_as_float(r32[j0 + jj]) + sbias[col0 + j0 + jj];
                    v = fmaxf(v, 0.f);
                    hv[jj] = __float2bfloat16(v);
                    lv[jj] = __float2bfloat16(v - __bfloat162float(hv[jj]));
                }
                size_t o = grow * CO + n0 + col0 + j0;
                *(uint4*)(oHi + o) = *(const uint4*)hv;
                *(uint4*)(oLo + o) = *(const uint4*)lv;
            } else {
                float ov[8];
                #pragma unroll
                for (int jj = 0; jj < 8; jj++) {
                    float v = __uint_as_float(r32[j0 + jj]) + sbias[col0 + j0 + jj];
                    ov[jj] = fmaxf(v, 0.f);
                }
                size_t o = grow * CO + n0 + col0 + j0;
                *(float4*)(oF + o)     = *(const float4*)(ov);
                *(float4*)(oF + o + 4) = *(const float4*)(ov + 4);
            }
        }
    }

    __syncthreads();
    if (wid == 0) {
        TCGEN05_RELINQUISH_ALLOC_PERMIT();
        TCGEN05_DEALLOC(tmem, 128);
    }
#endif // HAS_TCGEN05
}

// ---------------------------------------------------------------------------
// out = tanh(out2 @ W3 + b3)   [B,T,1]
// ---------------------------------------------------------------------------
__global__ __launch_bounds__(128) void k_head3(const float* __restrict__ W3,
                                               const float* __restrict__ b3,
                                               float* __restrict__ out)
{
    int row  = blockIdx.x * 4 + (threadIdx.x >> 5);
    int lane = threadIdx.x & 31;
    const float* p = g_out2 + (size_t)row * 256;
    float s = 0.f;
    #pragma unroll
    for (int i = 0; i < 8; i++) s = fmaf(p[lane + 32 * i], W3[lane + 32 * i], s);
    #pragma unroll
    for (int o = 16; o; o >>= 1) s += __shfl_xor_sync(0xffffffffu, s, o);
    if (lane == 0) out[row] = tanhf(s + b3[0]);
}

// ---------------------------------------------------------------------------
extern "C" void kernel_launch(void* const* d_in, const int* in_sizes, int n_in,
                              void* d_out, int out_size) {
    const float* x     = (const float*)d_in[0];
    const float* cond  = (const float*)d_in[1];
    const float* Wc    = (const float*)d_in[2];
    const float* bc    = (const float*)d_in[3];
    const float* Wt    = (const float*)d_in[4];
    const float* bt    = (const float*)d_in[5];
    const float* Ws    = (const float*)d_in[6];
    const float* bs    = (const float*)d_in[7];
    const float* Dt    = (const float*)d_in[8];
    const float* Bt    = (const float*)d_in[9];
    const float* Ds    = (const float*)d_in[10];
    const float* Bs    = (const float*)d_in[11];
    const float* Wskip = (const float*)d_in[12];
    const float* bskip = (const float*)d_in[13];
    const float* Wres  = (const float*)d_in[14];
    const float* bres  = (const float*)d_in[15];
    const float* W1    = (const float*)d_in[16];
    const float* b1    = (const float*)d_in[17];
    const float* W2    = (const float*)d_in[18];
    const float* b2    = (const float*)d_in[19];
    const float* W3    = (const float*)d_in[20];
    const float* b3    = (const float*)d_in[21];
    float* out = (float*)d_out;

    cudaFuncSetAttribute(k_gemm<true>,  cudaFuncAttributeMaxDynamicSharedMemorySize, GEMM_SMEM);
    cudaFuncSetAttribute(k_gemm<false>, cudaFuncAttributeMaxDynamicSharedMemorySize, GEMM_SMEM);

    __nv_bfloat16 *skipHi, *skipLo, *w1h, *w1l, *w2h, *w2l, *o1h, *o1l;
    float* out2p;
    cudaGetSymbolAddress((void**)&skipHi, g_skipHi);
    cudaGetSymbolAddress((void**)&skipLo, g_skipLo);
    cudaGetSymbolAddress((void**)&w1h, g_W1tHi);
    cudaGetSymbolAddress((void**)&w1l, g_W1tLo);
    cudaGetSymbolAddress((void**)&w2h, g_W2tHi);
    cudaGetSymbolAddress((void**)&w2l, g_W2tLo);
    cudaGetSymbolAddress((void**)&o1h, g_out1Hi);
    cudaGetSymbolAddress((void**)&o1l, g_out1Lo);
    cudaGetSymbolAddress((void**)&out2p, g_out2);

    // head-weight transforms (independent of the stack)
    k_cvtW<<<dim3(2048/32, 128/32, 3), dim3(32, 8)>>>(W1, w1h, w1l, 128, 2048);
    k_cvtW<<<dim3(256/32, 2048/32, 3), dim3(32, 8)>>>(W2, w2h, w2l, 2048, 256);

    k_init<<<NB * TT * NC / 256, 256>>>(x, Wc, bc);

    const int dil[NL] = {1, 2, 4, 8, 16, 32, 64, 128, 256, 512};
    for (int l = 0; l < NL; l++) {
        k_gated<<<dim3(TT / 4, 2), 128>>>(Wt, bt, Ws, bs, Dt, Bt, Ds, Bs, cond, l, dil[l]);
        k_post<<<NB * TT / 32, 128>>>(Wskip, bskip, Wres, bres, l);
    }

    k_cvtA<<<NB * TT * NC / 1024, 256>>>();

    // head1: [B*T, 3x128] x [384,2048] -> out1 (bf16 split), relu
    k_gemm<true><<<dim3(128, 16), 256, GEMM_SMEM>>>(
        skipHi, skipLo, w1h, w1l, b1, o1h, o1l, nullptr, 128, 2048);
    // head2: [B*T, 3x2048] x [6144,256] -> out2 (fp32), relu
    k_gemm<false><<<dim3(128, 2), 256, GEMM_SMEM>>>(
        o1h, o1l, w2h, w2l, b2, nullptr, nullptr, out2p, 2048, 256);

    k_head3<<<NB * TT / 4, 128>>>(W3, b3, out);
}

// round 4
// speedup vs baseline: 2.3258x; 1.5042x over previous
#include <cuda_runtime.h>
#include <cuda_bf16.h>
#include <math.h>
#include <stdint.h>

#define TT    2048
#define NB    8
#define NC    128
#define NCOND 16
#define NL    10

// tcgen05 only exists in the arch-specific (sm_10xa) compile passes.
#if defined(__CUDA_ARCH_FEAT_SM103_ALL) || defined(__CUDA_ARCH_FEAT_SM100_ALL) || defined(__CUDA_ARCH_FEAT_SM101_ALL)
#define HAS_TCGEN05 1
#else
#define HAS_TCGEN05 0
#endif

typedef unsigned long long u64;

// ---------------------------------------------------------------------------
// Device scratch (allocation-free)
// ---------------------------------------------------------------------------
__device__ float g_h   [NB*TT*NC];
__device__ float g_skip[NB*TT*NC];
__device__ float g_out2[NB*TT*256];
__device__ float g_tcond[(size_t)NL*NB*TT*256];          // 168 MB

__device__ __nv_bfloat16 g_hHi  [NB*TT*NC];
__device__ __nv_bfloat16 g_hLo  [NB*TT*NC];
__device__ __nv_bfloat16 g_WgHi [NL*3*256*128];          // [l][tap][n=256][ci]
__device__ __nv_bfloat16 g_WgLo [NL*3*256*128];
__device__ __nv_bfloat16 g_WpHi [NL*256*128];            // [l][n=256][ci]
__device__ __nv_bfloat16 g_WpLo [NL*256*128];

__device__ __nv_bfloat16 g_skipHi[NB*TT*NC];
__device__ __nv_bfloat16 g_skipLo[NB*TT*NC];
__device__ __nv_bfloat16 g_W1tHi [3*2048*128];           // [tap][co][ci]
__device__ __nv_bfloat16 g_W1tLo [3*2048*128];
__device__ __nv_bfloat16 g_W2tHi [3*256*2048];           // [tap][co][ci]
__device__ __nv_bfloat16 g_W2tLo [3*256*2048];
__device__ __nv_bfloat16 g_out1Hi[(size_t)NB*TT*2048];
__device__ __nv_bfloat16 g_out1Lo[(size_t)NB*TT*2048];

// ---------------------------------------------------------------------------
// helpers
// ---------------------------------------------------------------------------
__device__ __forceinline__ uint32_t smem_to_u32(const void* p) {
    uint32_t a;
    asm("{ .reg .u64 t; cvta.to.shared.u64 t, %1; cvt.u32.u64 %0, t; }"
        : "=r"(a) : "l"(p));
    return a;
}

#if HAS_TCGEN05
__device__ __forceinline__ uint32_t elect_one_pred() {
    uint32_t pred;
    asm volatile(
        "{\n\t.reg .pred p;\n\telect.sync _|p, 0xFFFFFFFF;\n\t"
        "selp.b32 %0, 1, 0, p;\n\t}" : "=r"(pred));
    return pred;
}

#define TCGEN05_ALLOC(smem_result_addr, nCols) \
    asm volatile("tcgen05.alloc.cta_group::1.sync.aligned.shared::cta.b32 [%0], %1;" \
        :: "r"((uint32_t)(smem_result_addr)), "r"((uint32_t)(nCols)) : "memory")
#define TCGEN05_DEALLOC(tmem_addr, nCols) \
    asm volatile("tcgen05.dealloc.cta_group::1.sync.aligned.b32 %0, %1;" \
        :: "r"(tmem_addr), "r"((uint32_t)(nCols)))
#define TCGEN05_RELINQUISH_ALLOC_PERMIT() \
    asm volatile("tcgen05.relinquish_alloc_permit.cta_group::1.sync.aligned;")
#define TCGEN05_COMMIT(mbar_smem_addr) \
    asm volatile("tcgen05.commit.cta_group::1.mbarrier::arrive::one.shared::cluster.b64 [%0];" \
        :: "r"((uint32_t)(mbar_smem_addr)) : "memory")
#define TCGEN05_FENCE_AFTER() \
    asm volatile("tcgen05.fence::after_thread_sync;" ::: "memory")
#define TCGEN05_WAIT_LD() \
    asm volatile("tcgen05.wait::ld.sync.aligned;" ::: "memory")
#define FENCE_PROXY_ASYNC_SHARED_CTA() \
    asm volatile("fence.proxy.async.shared::cta;" ::: "memory")
#define MBARRIER_INIT(mbar_smem_addr, count) \
    asm volatile("mbarrier.init.shared.b64 [%0], %1;" \
        :: "r"((uint32_t)(mbar_smem_addr)), "r"((uint32_t)(count)) : "memory")

#define MBARRIER_WAIT_PARITY(mbar_smem_addr, phase_parity) do { \
    uint32_t _mbar = (uint32_t)(mbar_smem_addr); \
    uint32_t _parity = (uint32_t)(phase_parity); \
    uint32_t _done; \
    asm volatile( \
        "{\n\t.reg .pred p;\n\t" \
        "mbarrier.try_wait.parity.acquire.cta.shared::cta.b64 p, [%1], %2;\n\t" \
        "selp.b32 %0, 1, 0, p;\n\t}" \
        : "=r"(_done) : "r"(_mbar), "r"(_parity) : "memory"); \
    if (!_done) { \
        asm volatile( \
            "{\n\t.reg .pred P1;\n\t" \
            "WAIT_LOOP_%=:\n\t" \
            "mbarrier.try_wait.parity.acquire.cta.shared::cta.b64 P1, [%0], %1, 0x989680;\n\t" \
            "@P1 bra.uni WAIT_DONE_%=;\n\t" \
            "bra.uni WAIT_LOOP_%=;\n\t" \
            "WAIT_DONE_%=:\n\t}" \
            :: "r"(_mbar), "r"(_parity) : "memory"); \
    } \
} while(0)

#define TCGEN05_LD_32X32B_X32(r, tmem_addr) \
    asm volatile( \
        "tcgen05.ld.sync.aligned.32x32b.x32.b32 " \
        "{%0, %1, %2, %3, %4, %5, %6, %7, " \
        " %8, %9, %10, %11, %12, %13, %14, %15, " \
        " %16, %17, %18, %19, %20, %21, %22, %23, " \
        " %24, %25, %26, %27, %28, %29, %30, %31}, [%32];" \
        : "=r"((r)[0]),  "=r"((r)[1]),  "=r"((r)[2]),  "=r"((r)[3]), \
          "=r"((r)[4]),  "=r"((r)[5]),  "=r"((r)[6]),  "=r"((r)[7]), \
          "=r"((r)[8]),  "=r"((r)[9]),  "=r"((r)[10]), "=r"((r)[11]), \
          "=r"((r)[12]), "=r"((r)[13]), "=r"((r)[14]), "=r"((r)[15]), \
          "=r"((r)[16]), "=r"((r)[17]), "=r"((r)[18]), "=r"((r)[19]), \
          "=r"((r)[20]), "=r"((r)[21]), "=r"((r)[22]), "=r"((r)[23]), \
          "=r"((r)[24]), "=r"((r)[25]), "=r"((r)[26]), "=r"((r)[27]), \
          "=r"((r)[28]), "=r"((r)[29]), "=r"((r)[30]), "=r"((r)[31]) \
        : "r"(tmem_addr))

static constexpr unsigned long long SMEM_DESC_BASE_SW128 =
    (2ull << 61) | (1ull << 46) | (64ull << 32) | (1ull << 16);
#define MAKE_SMEM_DESC(a) (SMEM_DESC_BASE_SW128 | ((unsigned long long)((a) >> 4) & 0x3FFF))

__device__ __forceinline__ void mma_bf16_ss(uint32_t d, u64 ad, u64 bd,
                                            uint32_t idesc, uint32_t en) {
    asm volatile(
        "{\n\t.reg .pred p;\n\t"
        "setp.ne.u32 p, %4, 0;\n\t"
        "tcgen05.mma.cta_group::1.kind::f16 [%0], %1, %2, %3, {%5, %5, %5, %5}, p;\n\t"
        "}"
        :: "r"(d), "l"(ad), "l"(bd), "r"(idesc), "r"(en), "r"(0u)
        : "memory");
}

// idesc: dtype F32(bit4), atype BF16(bit7), btype BF16(bit10), N/8<<17, M/16<<24
static constexpr uint32_t GEMM_IDESC =
    (1u << 4) | (1u << 7) | (1u << 10) | ((128u / 8) << 17) | ((128u / 16) << 24);
static constexpr uint32_t IDESC_N256 =
    (1u << 4) | (1u << 7) | (1u << 10) | ((256u / 8) << 17) | ((128u / 16) << 24);
#endif // HAS_TCGEN05

// ---------------------------------------------------------------------------
// h = x * Wc + bc (fp32 + bf16 split) ;  skip_sum = 0
// ---------------------------------------------------------------------------
__global__ __launch_bounds__(256) void k_init(const float* __restrict__ x,
                                              const float* __restrict__ Wc,
                                              const float* __restrict__ bc) {
    int idx = blockIdx.x * 256 + threadIdx.x;
    int c  = idx & (NC - 1);
    int bt = idx >> 7;
    float v = x[bt] * Wc[c] + bc[c];
    g_h[idx]    = v;
    g_skip[idx] = 0.f;
    __nv_bfloat16 h = __float2bfloat16(v);
    g_hHi[idx] = h;
    g_hLo[idx] = __float2bfloat16(v - __bfloat162float(h));
}

// ---------------------------------------------------------------------------
// Stack weight conversion: Wt/Ws [L,3,ci,co] -> g_Wg [l*3+tap][n=co(+128s)][ci]
// ---------------------------------------------------------------------------
__global__ void k_cvtWg(const float* __restrict__ Wt, const float* __restrict__ Ws) {
    int lt = blockIdx.z >> 1, gate = blockIdx.z & 1;
    const float* src = (gate ? Ws : Wt) + (size_t)lt * 128 * 128;
    __shared__ float t[32][33];
    int co0 = blockIdx.x * 32, ci0 = blockIdx.y * 32;
    int tx = threadIdx.x, ty = threadIdx.y;
    #pragma unroll
    for (int r = 0; r < 4; r++)
        t[ty + r*8][tx] = src[(ci0 + ty + r*8) * 128 + co0 + tx];
    __syncthreads();
    #pragma unroll
    for (int r = 0; r < 4; r++) {
        float v = t[tx][ty + r*8];
        int n = gate * 128 + co0 + ty + r*8;
        size_t o = ((size_t)lt * 256 + n) * 128 + ci0 + tx;
        __nv_bfloat16 h = __float2bfloat16(v);
        g_WgHi[o] = h;
        g_WgLo[o] = __float2bfloat16(v - __bfloat162float(h));
    }
}

__global__ void k_cvtWp(const float* __restrict__ Wskip, const float* __restrict__ Wres) {
    int l = blockIdx.z >> 1, gate = blockIdx.z & 1;
    const float* src = (gate ? Wres : Wskip) + (size_t)l * 128 * 128;
    __shared__ float t[32][33];
    int co0 = blockIdx.x * 32, ci0 = blockIdx.y * 32;
    int tx = threadIdx.x, ty = threadIdx.y;
    #pragma unroll
    for (int r = 0; r < 4; r++)
        t[ty + r*8][tx] = src[(ci0 + ty + r*8) * 128 + co0 + tx];
    __syncthreads();
    #pragma unroll
    for (int r = 0; r < 4; r++) {
        float v = t[tx][ty + r*8];
        int n = gate * 128 + co0 + ty + r*8;
        size_t o = ((size_t)l * 256 + n) * 128 + ci0 + tx;
        __nv_bfloat16 h = __float2bfloat16(v);
        g_WpHi[o] = h;
        g_WpLo[o] = __float2bfloat16(v - __bfloat162float(h));
    }
}

// ---------------------------------------------------------------------------
// tcond[l][b][t][n] = sum_c cond[b,c] D[l,c,t,n'] + B[l,t,n'] + bias[l,n']
//   n<128 -> (Dt,Bt,bt), n>=128 -> (Ds,Bs,bs)
// ---------------------------------------------------------------------------
__global__ __launch_bounds__(256) void k_condpre(
    const float* __restrict__ cond,
    const float* __restrict__ Dt, const float* __restrict__ Ds,
    const float* __restrict__ Bt, const float* __restrict__ Bs,
    const float* __restrict__ bt, const float* __restrict__ bs)
{
    int l = blockIdx.y;
    int t2 = blockIdx.x * 2;
    int cop = threadIdx.x;
    int gate = cop >> 7, co = cop & 127;
    __shared__ float sc[NB][NCOND];
    if (cop < NB * NCOND) sc[cop >> 4][cop & 15] = cond[cop];
    __syncthreads();

    const float* D  = gate ? Ds : Dt;
    const float* Bm = gate ? Bs : Bt;
    float bias = (gate ? bs : bt)[l * 128 + co];

    float acc[2][NB];
    #pragma unroll
    for (int tt = 0; tt < 2; tt++)
        #pragma unroll
        for (int b = 0; b < NB; b++) acc[tt][b] = 0.f;

    #pragma unroll 4
    for (int c = 0; c < NCOND; c++) {
        size_t base = (((size_t)l * NCOND + c) * TT + t2) * 128 + co;
        float d0 = D[base], d1 = D[base + 128];
        #pragma unroll
        for (int b = 0; b < NB; b++) {
            acc[0][b] = fmaf(sc[b][c], d0, acc[0][b]);
            acc[1][b] = fmaf(sc[b][c], d1, acc[1][b]);
        }
    }
    #pragma unroll
    for (int tt = 0; tt < 2; tt++) {
        float bm = Bm[((size_t)l * TT + t2 + tt) * 128 + co] + bias;
        #pragma unroll
        for (int b = 0; b < NB; b++)
            g_tcond[(((size_t)l * NB + b) * TT + t2 + tt) * 256 + cop] = acc[tt][b] + bm;
    }
}

// ---------------------------------------------------------------------------
// Fused residual layer (tcgen05):
//  D1 = gateMMA(h_split, Wg)          (N=256: [tanh|sigmoid] preacts)
//  g  = tanh(D1t + tcond_t) * sigmoid(D1s + tcond_s)  -> bf16 split A-tiles
//  D2 = postMMA(g_split, Wp)          (N=256: [skip|res])
//  skip += D2s; h += D2r (fp32) ; h split refreshed
// ---------------------------------------------------------------------------
#define LAYER_SMEM (2048 + 2*98304)

__global__ __launch_bounds__(256) void k_layer(int l, int d)
{
#if HAS_TCGEN05
    extern __shared__ char dsm[];
    const int tid = threadIdx.x;
    const int wid = tid >> 5;

    uint32_t raw = smem_to_u32(dsm);
    uint32_t abase = (raw + 1023) & ~1023u;
    char* hdr = dsm + (abase - raw);
    char* G   = hdr + 2048;
    const uint32_t hdr_a = abase;
    const uint32_t G_a   = abase + 2048;

    const int b  = blockIdx.x >> 4;
    const int t0 = (blockIdx.x & 15) << 7;

    if (tid == 0) {
        MBARRIER_INIT(hdr_a + 8, 1);
        MBARRIER_INIT(hdr_a + 16, 1);
    }
    if (wid == 0) TCGEN05_ALLOC(hdr_a, 512);
    __syncthreads();

    uint32_t tmem;
    asm volatile("ld.shared.b32 %0, [%1];" : "=r"(tmem) : "r"(hdr_a));

    int phase[2] = {0, 0};

    // ---- gate phase: 6 chunks (3 taps x 2 ci-halves), double-buffered ----
    for (int ch = 0; ch < 6; ch++) {
        const int buf = ch & 1;
        char* Gb = G + buf * 98304;
        const uint32_t Gb_a = G_a + buf * 98304;

        if (ch >= 2) {
            MBARRIER_WAIT_PARITY(hdr_a + 8 + 8 * buf, phase[buf]);
            phase[buf] ^= 1;
        }

        const int tap = ch >> 1;
        const int ci0 = (ch & 1) << 6;

        // A: h split, rows shifted by (tap-1)*d  (each thread = half row)
        {
            int r = tid >> 1, half = tid & 1;
            int trow = t0 + r + (tap - 1) * d;
            bool ok = (unsigned)trow < (unsigned)TT;
            size_t goff = ((size_t)(b * TT + (ok ? trow : 0))) * NC + ci0 + half * 32;
            #pragma unroll
            for (int q = 0; q < 4; q++) {
                int c = half * 4 + q;
                uint32_t so = r * 128 + (((uint32_t)(c ^ (r & 7))) << 4);
                uint4 vh = make_uint4(0,0,0,0), vl = make_uint4(0,0,0,0);
                if (ok) {
                    vh = *(const uint4*)(g_hHi + goff + q * 8);
                    vl = *(const uint4*)(g_hLo + goff + q * 8);
                }
                *(uint4*)(Gb + so)         = vh;
                *(uint4*)(Gb + 16384 + so) = vl;
            }
        }
        // B: gate weights, 256 rows (one per thread)
        {
            size_t woff = (((size_t)(l * 3 + tap)) * 256 + tid) * 128 + ci0;
            #pragma unroll
            for (int q = 0; q < 8; q++) {
                uint32_t so = tid * 128 + (((uint32_t)(q ^ (tid & 7))) << 4);
                *(uint4*)(Gb + 32768 + so) = *(const uint4*)(g_WgHi + woff + q * 8);
                *(uint4*)(Gb + 65536 + so) = *(const uint4*)(g_WgLo + woff + q * 8);
            }
        }
        FENCE_PROXY_ASYNC_SHARED_CTA();
        __syncthreads();

        if (wid == 0 && elect_one_pred()) {
            u64 dAh = MAKE_SMEM_DESC(Gb_a);
            u64 dAl = MAKE_SMEM_DESC(Gb_a + 16384);
            u64 dBh = MAKE_SMEM_DESC(Gb_a + 32768);
            u64 dBl = MAKE_SMEM_DESC(Gb_a + 65536);
            uint32_t en = (ch != 0);
            #pragma unroll
            for (int ks = 0; ks < 4; ks++) {
                mma_bf16_ss(tmem, dAh + 2*ks, dBh + 2*ks, IDESC_N256, en); en = 1;
                mma_bf16_ss(tmem, dAh + 2*ks, dBl + 2*ks, IDESC_N256, 1);
                mma_bf16_ss(tmem, dAl + 2*ks, dBh + 2*ks, IDESC_N256, 1);
            }
            TCGEN05_COMMIT(hdr_a + 8 + 8 * buf);
        }
    }

    MBARRIER_WAIT_PARITY(hdr_a + 8,  phase[0]);
    MBARRIER_WAIT_PARITY(hdr_a + 16, phase[1]);
    const int postPh = phase[0] ^ 1;
    TCGEN05_FENCE_AFTER();
    __syncthreads();

    // ---- load post weights into G[64K,192K) (all threads) ----
    {
        size_t woff = ((size_t)l * 256 + tid) * 128;
        #pragma unroll
        for (int cc = 0; cc < 2; cc++) {
            char* dst = G + 65536 + cc * 65536;
            #pragma unroll
            for (int q = 0; q < 8; q++) {
                uint32_t so = tid * 128 + (((uint32_t)(q ^ (tid & 7))) << 4);
                *(uint4*)(dst + so)         = *(const uint4*)(g_WpHi + woff + cc*64 + q*8);
                *(uint4*)(dst + 32768 + so) = *(const uint4*)(g_WpLo + woff + cc*64 + q*8);
            }
        }
    }

    // ---- epilogue 1: g = tanh * sigmoid, split into A-tiles at G[0,64K) ----
    if (tid < 128) {
        const int row = tid;                 // warp w covers rows w*32..w*32+31
        const float* tc = g_tcond + (((size_t)l * NB + b) * TT + t0 + row) * 256;
        #pragma unroll 1
        for (int s = 0; s < 4; s++) {
            uint32_t r1[32], r2[32];
            TCGEN05_LD_32X32B_X32(r1, tmem + s * 32);
            TCGEN05_LD_32X32B_X32(r2, tmem + 128 + s * 32);
            TCGEN05_WAIT_LD();
            #pragma unroll
            for (int j = 0; j < 32; j += 4) {
                int col = s * 32 + j;
                float4 ta = *(const float4*)(tc + col);
                float4 tsg = *(const float4*)(tc + 128 + col);
                float a[4] = {__uint_as_float(r1[j])   + ta.x,
                              __uint_as_float(r1[j+1]) + ta.y,
                              __uint_as_float(r1[j+2]) + ta.z,
                              __uint_as_float(r1[j+3]) + ta.w};
                float sgv[4] = {__uint_as_float(r2[j])   + tsg.x,
                                __uint_as_float(r2[j+1]) + tsg.y,
                                __uint_as_float(r2[j+2]) + tsg.z,
                                __uint_as_float(r2[j+3]) + tsg.w};
                __nv_bfloat16 hv[4], lv[4];
                #pragma unroll
                for (int q = 0; q < 4; q++) {
                    float gv = tanhf(a[q]) / (1.f + expf(-sgv[q]));
                    hv[q] = __float2bfloat16(gv);
                    lv[q] = __float2bfloat16(gv - __bfloat162float(hv[q]));
                }
                uint32_t off = row * 128 + (col & 63) * 2;
                off ^= (off >> 3) & 0x70;
                char* atp = G + ((col >> 6) * 32768);
                *(uint2*)(atp + off)         = *(const uint2*)hv;
                *(uint2*)(atp + 16384 + off) = *(const uint2*)lv;
            }
        }
    }
    FENCE_PROXY_ASYNC_SHARED_CTA();
    __syncthreads();

    // ---- post MMA: D2 (cols 256..511) ----
    if (wid == 0 && elect_one_pred()) {
        uint32_t en = 0;
        #pragma unroll
        for (int cc = 0; cc < 2; cc++) {
            u64 dAh = MAKE_SMEM_DESC(G_a + cc * 32768);
            u64 dAl = MAKE_SMEM_DESC(G_a + cc * 32768 + 16384);
            u64 dBh = MAKE_SMEM_DESC(G_a + 65536 + cc * 65536);
            u64 dBl = MAKE_SMEM_DESC(G_a + 65536 + cc * 65536 + 32768);
            #pragma unroll
            for (int ks = 0; ks < 4; ks++) {
                mma_bf16_ss(tmem + 256, dAh + 2*ks, dBh + 2*ks, IDESC_N256, en); en = 1;
                mma_bf16_ss(tmem + 256, dAh + 2*ks, dBl + 2*ks, IDESC_N256, 1);
                mma_bf16_ss(tmem + 256, dAl + 2*ks, dBh + 2*ks, IDESC_N256, 1);
            }
        }
        TCGEN05_COMMIT(hdr_a + 8);
    }
    MBARRIER_WAIT_PARITY(hdr_a + 8, postPh);
    TCGEN05_FENCE_AFTER();

    // ---- epilogue 2: skip += D2s + bskip ; h += D2r + bres ; refresh split ----
    if (tid < 128) {
        const int row = tid;
        const size_t gr = ((size_t)(b * TT + t0 + row)) * NC;
        #pragma unroll 1
        for (int s = 0; s < 4; s++) {
            uint32_t r1[32], r2[32];
            TCGEN05_LD_32X32B_X32(r1, tmem + 256 + s * 32);
            TCGEN05_LD_32X32B_X32(r2, tmem + 256 + 128 + s * 32);
            TCGEN05_WAIT_LD();
            #pragma unroll
            for (int j = 0; j < 32; j += 4) {
                int col = s * 32 + j;
                float4 sk = *(const float4*)(g_skip + gr + col);
                float4 hh = *(const float4*)(g_h + gr + col);
                sk.x += __uint_as_float(r1[j]);
                sk.y += __uint_as_float(r1[j+1]);
                sk.z += __uint_as_float(r1[j+2]);
                sk.w += __uint_as_float(r1[j+3]);
                hh.x += __uint_as_float(r2[j]);
                hh.y += __uint_as_float(r2[j+1]);
                hh.z += __uint_as_float(r2[j+2]);
                hh.w += __uint_as_float(r2[j+3]);
                *(float4*)(g_skip + gr + col) = sk;
                *(float4*)(g_h + gr + col) = hh;
                float hq[4] = {hh.x, hh.y, hh.z, hh.w};
                __nv_bfloat16 hv[4], lv[4];
                #pragma unroll
                for (int q = 0; q < 4; q++) {
                    hv[q] = __float2bfloat16(hq[q]);
                    lv[q] = __float2bfloat16(hq[q] - __bfloat162float(hv[q]));
                }
                *(uint2*)(g_hHi + gr + col) = *(const uint2*)hv;
                *(uint2*)(g_hLo + gr + col) = *(const uint2*)lv;
            }
        }
    }
    __syncthreads();
    if (wid == 0) {
        TCGEN05_RELINQUISH_ALLOC_PERMIT();
        TCGEN05_DEALLOC(tmem, 512);
    }
#endif // HAS_TCGEN05
}

// ---------------------------------------------------------------------------
// fp32 -> bf16 hi/lo split of skip_sum
// ---------------------------------------------------------------------------
__global__ __launch_bounds__(256) void k_cvtA() {
    int i = (blockIdx.x * 256 + threadIdx.x) * 4;
    float4 v = *(const float4*)(g_skip + i);
    __nv_bfloat16 h[4], l[4];
    float vv[4] = {v.x, v.y, v.z, v.w};
    #pragma unroll
    for (int j = 0; j < 4; j++) {
        h[j] = __float2bfloat16(vv[j]);
        l[j] = __float2bfloat16(vv[j] - __bfloat162float(h[j]));
    }
    *(uint2*)(g_skipHi + i) = *(const uint2*)h;
    *(uint2*)(g_skipLo + i) = *(const uint2*)l;
}

// ---------------------------------------------------------------------------
// Transpose + split head weights: src [3,K,N] fp32 -> dst [3,N,K] bf16 hi/lo
// ---------------------------------------------------------------------------
__global__ void k_cvtW(const float* __restrict__ src,
                       __nv_bfloat16* __restrict__ dhi,
                       __nv_bfloat16* __restrict__ dlo, int K, int N) {
    __shared__ float t[32][33];
    int tap = blockIdx.z;
    int n0 = blockIdx.x * 32, k0 = blockIdx.y * 32;
    int tx = threadIdx.x, ty = threadIdx.y;
    #pragma unroll
    for (int r = 0; r < 4; r++)
        t[ty + r*8][tx] = src[((size_t)tap*K + k0 + ty + r*8) * N + n0 + tx];
    __syncthreads();
    #pragma unroll
    for (int r = 0; r < 4; r++) {
        float v = t[tx][ty + r*8];
        __nv_bfloat16 h = __float2bfloat16(v);
        __nv_bfloat16 l = __float2bfloat16(v - __bfloat162float(h));
        size_t o = ((size_t)tap*N + n0 + ty + r*8) * K + k0 + tx;
        dhi[o] = h; dlo[o] = l;
    }
}

// ---------------------------------------------------------------------------
// tcgen05 GEMM-conv3 head kernel (unchanged from round 3)
// ---------------------------------------------------------------------------
#define GEMM_SMEM (1024 + 1024 + 131072)

template<bool WB16>
__global__ __launch_bounds__(256) void k_gemm(
    const __nv_bfloat16* __restrict__ aHi, const __nv_bfloat16* __restrict__ aLo,
    const __nv_bfloat16* __restrict__ wHi, const __nv_bfloat16* __restrict__ wLo,
    const float* __restrict__ bias,
    __nv_bfloat16* __restrict__ oHi, __nv_bfloat16* __restrict__ oLo,
    float* __restrict__ oF, int Cin, int CO)
{
#if HAS_TCGEN05
    extern __shared__ char dsm[];
    const int tid = threadIdx.x;
    const int wid = tid >> 5;
    const int lane = tid & 31;

    uint32_t raw = smem_to_u32(dsm);
    uint32_t abase = (raw + 1023) & ~1023u;
    char* hdr   = dsm + (abase - raw);
    char* tiles = hdr + 1024;
    const uint32_t hdr_a   = abase;
    const uint32_t tiles_a = abase + 1024;
    float* sbias = (float*)(hdr + 512);

    const int b  = blockIdx.x >> 4;
    const int t0 = (blockIdx.x & 15) * 128;
    const int n0 = blockIdx.y * 128;

    if (tid == 0) {
        MBARRIER_INIT(hdr_a + 8, 1);
        MBARRIER_INIT(hdr_a + 16, 1);
    }
    if (wid == 0) TCGEN05_ALLOC(hdr_a, 128);
    if (tid < 128) sbias[tid] = bias[n0 + tid];
    __syncthreads();

    uint32_t tmem;
    asm volatile("ld.shared.b32 %0, [%1];" : "=r"(tmem) : "r"(hdr_a));

    const int nci = Cin >> 6;
    const int nchunks = 3 * nci;
    const size_t aBatch = (size_t)b * TT * Cin;

    int phase[2] = {0, 0};

    for (int ch = 0; ch < nchunks; ch++) {
        const int buf = ch & 1;
        char* tb = tiles + buf * 65536;
        const uint32_t tb_a = tiles_a + buf * 65536;

        if (ch >= 2) {
            MBARRIER_WAIT_PARITY(hdr_a + 8 + 8 * buf, phase[buf]);
            phase[buf] ^= 1;
        }

        const int tap = ch / nci;
        const int ci0 = (ch - tap * nci) << 6;
        const size_t bBase = ((size_t)tap * CO + n0) * Cin + ci0;

        const int c = tid & 7;
        #pragma unroll
        for (int p = 0; p < 4; p++) {
            int r = p * 32 + (tid >> 3);
            uint32_t so = r * 128 + (((uint32_t)(c ^ (r & 7))) << 4);
            int trow = t0 + r + tap - 1;
            uint4 vah = make_uint4(0,0,0,0), val = make_uint4(0,0,0,0);
            if ((unsigned)trow < (unsigned)TT) {
                size_t off = aBatch + (size_t)trow * Cin + ci0 + c * 8;
                vah = *(const uint4*)(aHi + off);
                val = *(const uint4*)(aLo + off);
            }
            *(uint4*)(tb + so)         = vah;
            *(uint4*)(tb + 16384 + so) = val;
            size_t bo = bBase + (size_t)r * Cin + c * 8;
            *(uint4*)(tb + 32768 + so) = *(const uint4*)(wHi + bo);
            *(uint4*)(tb + 49152 + so) = *(const uint4*)(wLo + bo);
        }
        FENCE_PROXY_ASYNC_SHARED_CTA();
        __syncthreads();

        if (wid == 0 && elect_one_pred()) {
            u64 dAh = MAKE_SMEM_DESC(tb_a);
            u64 dAl = MAKE_SMEM_DESC(tb_a + 16384);
            u64 dBh = MAKE_SMEM_DESC(tb_a + 32768);
            u64 dBl = MAKE_SMEM_DESC(tb_a + 49152);
            uint32_t en = (ch != 0);
            #pragma unroll
            for (int ks = 0; ks < 4; ks++) {
                mma_bf16_ss(tmem, dAh + 2*ks, dBh + 2*ks, GEMM_IDESC, en); en = 1;
                mma_bf16_ss(tmem, dAh + 2*ks, dBl + 2*ks, GEMM_IDESC, 1);
                mma_bf16_ss(tmem, dAl + 2*ks, dBh + 2*ks, GEMM_IDESC, 1);
            }
            TCGEN05_COMMIT(hdr_a + 8 + 8 * buf);
        }
    }

    MBARRIER_WAIT_PARITY(hdr_a + 8,  phase[0]);
    MBARRIER_WAIT_PARITY(hdr_a + 16, phase[1]);
    TCGEN05_FENCE_AFTER();

    const int m = (wid & 3) * 32 + lane;
    const size_t grow = (size_t)(b * TT + t0 + m);
    #pragma unroll
    for (int half = 0; half < 2; half++) {
        int col0 = (wid >> 2) * 64 + half * 32;
        uint32_t r32[32];
        TCGEN05_LD_32X32B_X32(r32, tmem + col0);
        TCGEN05_WAIT_LD();
        #pragma unroll
        for (int j0 = 0; j0 < 32; j0 += 8) {
            if (WB16) {
                __nv_bfloat16 hv[8], lv[8];
                #pragma unroll
                for (int jj = 0; jj < 8; jj++) {
                    float v = __uint_as_float(r32[j0 + jj]) + sbias[col0 + j0 + jj];
                    v = fmaxf(v, 0.f);
                    hv[jj] = __float2bfloat16(v);
                    lv[jj] = __float2bfloat16(v - __bfloat162float(hv[jj]));
                }
                size_t o = grow * CO + n0 + col0 + j0;
                *(uint4*)(oHi + o) = *(const uint4*)hv;
                *(uint4*)(oLo + o) = *(const uint4*)lv;
            } else {
                float ov[8];
                #pragma unroll
                for (int jj = 0; jj < 8; jj++) {
                    float v = __uint_as_float(r32[j0 + jj]) + sbias[col0 + j0 + jj];
                    ov[jj] = fmaxf(v, 0.f);
                }
                size_t o = grow * CO + n0 + col0 + j0;
                *(float4*)(oF + o)     = *(const float4*)(ov);
                *(float4*)(oF + o + 4) = *(const float4*)(ov + 4);
            }
        }
    }

    __syncthreads();
    if (wid == 0) {
        TCGEN05_RELINQUISH_ALLOC_PERMIT();
        TCGEN05_DEALLOC(tmem, 128);
    }
#endif // HAS_TCGEN05
}

// ---------------------------------------------------------------------------
// out = tanh(out2 @ W3 + b3)   [B,T,1]
// ---------------------------------------------------------------------------
__global__ __launch_bounds__(128) void k_head3(const float* __restrict__ W3,
                                               const float* __restrict__ b3,
                                               float* __restrict__ out)
{
    int row  = blockIdx.x * 4 + (threadIdx.x >> 5);
    int lane = threadIdx.x & 31;
    const float* p = g_out2 + (size_t)row * 256;
    float s = 0.f;
    #pragma unroll
    for (int i = 0; i < 8; i++) s = fmaf(p[lane + 32 * i], W3[lane + 32 * i], s);
    #pragma unroll
    for (int o = 16; o; o >>= 1) s += __shfl_xor_sync(0xffffffffu, s, o);
    if (lane == 0) out[row] = tanhf(s + b3[0]);
}

// ---------------------------------------------------------------------------
extern "C" void kernel_launch(void* const* d_in, const int* in_sizes, int n_in,
                              void* d_out, int out_size) {
    const float* x     = (const float*)d_in[0];
    const float* cond  = (const float*)d_in[1];
    const float* Wc    = (const float*)d_in[2];
    const float* bc    = (const float*)d_in[3];
    const float* Wt    = (const float*)d_in[4];
    const float* bt    = (const float*)d_in[5];
    const float* Ws    = (const float*)d_in[6];
    const float* bs    = (const float*)d_in[7];
    const float* Dt    = (const float*)d_in[8];
    const float* Bt    = (const float*)d_in[9];
    const float* Ds    = (const float*)d_in[10];
    const float* Bs    = (const float*)d_in[11];
    const float* Wskip = (const float*)d_in[12];
    const float* bskip = (const float*)d_in[13];
    const float* Wres  = (const float*)d_in[14];
    const float* bres  = (const float*)d_in[15];
    const float* W1    = (const float*)d_in[16];
    const float* b1    = (const float*)d_in[17];
    const float* W2    = (const float*)d_in[18];
    const float* b2    = (const float*)d_in[19];
    const float* W3    = (const float*)d_in[20];
    const float* b3    = (const float*)d_in[21];
    float* out = (float*)d_out;

    cudaFuncSetAttribute(k_gemm<true>,  cudaFuncAttributeMaxDynamicSharedMemorySize, GEMM_SMEM);
    cudaFuncSetAttribute(k_gemm<false>, cudaFuncAttributeMaxDynamicSharedMemorySize, GEMM_SMEM);
    cudaFuncSetAttribute(k_layer, cudaFuncAttributeMaxDynamicSharedMemorySize, LAYER_SMEM);

    __nv_bfloat16 *skipHi, *skipLo, *w1h, *w1l, *w2h, *w2l, *o1h, *o1l;
    float* out2p;
    cudaGetSymbolAddress((void**)&skipHi, g_skipHi);
    cudaGetSymbolAddress((void**)&skipLo, g_skipLo);
    cudaGetSymbolAddress((void**)&w1h, g_W1tHi);
    cudaGetSymbolAddress((void**)&w1l, g_W1tLo);
    cudaGetSymbolAddress((void**)&w2h, g_W2tHi);
    cudaGetSymbolAddress((void**)&w2l, g_W2tLo);
    cudaGetSymbolAddress((void**)&o1h, g_out1Hi);
    cudaGetSymbolAddress((void**)&o1l, g_out1Lo);
    cudaGetSymbolAddress((void**)&out2p, g_out2);

    // weight transforms + conditioning precompute (independent of the stack)
    k_cvtWg<<<dim3(4, 4, NL * 3 * 2), dim3(32, 8)>>>(Wt, Ws);
    k_cvtWp<<<dim3(4, 4, NL * 2),     dim3(32, 8)>>>(Wskip, Wres);
    k_cvtW<<<dim3(2048/32, 128/32, 3),  dim3(32, 8)>>>(W1, w1h, w1l, 128, 2048);
    k_cvtW<<<dim3(256/32, 2048/32, 3),  dim3(32, 8)>>>(W2, w2h, w2l, 2048, 256);
    k_condpre<<<dim3(TT/2, NL), 256>>>(cond, Dt, Ds, Bt, Bs, bt, bs);

    k_init<<<NB * TT * NC / 256, 256>>>(x, Wc, bc);

    const int dil[NL] = {1, 2, 4, 8, 16, 32, 64, 128, 256, 512};
    for (int l = 0; l < NL; l++)
        k_layer<<<NB * (TT/128), 256, LAYER_SMEM>>>(l, dil[l]);

    k_cvtA<<<NB * TT * NC / 1024, 256>>>();

    // head1: [B*T, 3x128] x [384,2048] -> out1 (bf16 split), relu
    k_gemm<true><<<dim3(128, 16), 256, GEMM_SMEM>>>(
        skipHi, skipLo, w1h, w1l, b1, o1h, o1l, nullptr, 128, 2048);
    // head2: [B*T, 3x2048] x [6144,256] -> out2 (fp32), relu
    k_gemm<false><<<dim3(128, 2), 256, GEMM_SMEM>>>(
        o1h, o1l, w2h, w2l, b2, nullptr, nullptr, out2p, 2048, 256);

    k_head3<<<NB * TT / 4, 128>>>(W3, b3, out);
}

// round 5
// speedup vs baseline: 3.2258x; 1.3870x over previous
#include <cuda_runtime.h>
#include <cuda_bf16.h>
#include <math.h>
#include <stdint.h>

#define TT    2048
#define NB    8
#define NC    128
#define NCOND 16
#define NL    10

#if defined(__CUDA_ARCH_FEAT_SM103_ALL) || defined(__CUDA_ARCH_FEAT_SM100_ALL) || defined(__CUDA_ARCH_FEAT_SM101_ALL)
#define HAS_TCGEN05 1
#else
#define HAS_TCGEN05 0
#endif

typedef unsigned long long u64;

// ---------------------------------------------------------------------------
// Device scratch
// ---------------------------------------------------------------------------
__device__ float g_h   [NB*TT*NC];
__device__ float g_skip[NB*TT*NC];
__device__ float g_out2[NB*TT*256];
__device__ float g_tcond[(size_t)NL*NB*TT*256];

__device__ __nv_bfloat16 g_hHi  [NB*TT*NC];
__device__ __nv_bfloat16 g_hLo  [NB*TT*NC];
__device__ __nv_bfloat16 g_WgHi [NL*3*256*128];
__device__ __nv_bfloat16 g_WgLo [NL*3*256*128];
__device__ __nv_bfloat16 g_WpHi [NL*256*128];
__device__ __nv_bfloat16 g_WpLo [NL*256*128];

__device__ __nv_bfloat16 g_skipHi[NB*TT*NC];
__device__ __nv_bfloat16 g_skipLo[NB*TT*NC];
__device__ __nv_bfloat16 g_W1tHi [3*2048*128];
__device__ __nv_bfloat16 g_W1tLo [3*2048*128];
__device__ __nv_bfloat16 g_W2tHi [3*256*2048];
__device__ __nv_bfloat16 g_W2tLo [3*256*2048];
__device__ __nv_bfloat16 g_out1Hi[(size_t)NB*TT*2048];
__device__ __nv_bfloat16 g_out1Lo[(size_t)NB*TT*2048];

// ---------------------------------------------------------------------------
// helpers
// ---------------------------------------------------------------------------
__device__ __forceinline__ uint32_t smem_to_u32(const void* p) {
    uint32_t a;
    asm("{ .reg .u64 t; cvta.to.shared.u64 t, %1; cvt.u32.u64 %0, t; }"
        : "=r"(a) : "l"(p));
    return a;
}
__device__ __forceinline__ float tanh_fast(float a) {
    float e = __expf(2.f * a);
    return 1.f - __fdividef(2.f, e + 1.f);
}
__device__ __forceinline__ float sig_fast(float x) {
    return __fdividef(1.f, 1.f + __expf(-x));
}

#if HAS_TCGEN05
__device__ __forceinline__ uint32_t elect_one_pred() {
    uint32_t pred;
    asm volatile(
        "{\n\t.reg .pred p;\n\telect.sync _|p, 0xFFFFFFFF;\n\t"
        "selp.b32 %0, 1, 0, p;\n\t}" : "=r"(pred));
    return pred;
}

#define TCGEN05_ALLOC(smem_result_addr, nCols) \
    asm volatile("tcgen05.alloc.cta_group::1.sync.aligned.shared::cta.b32 [%0], %1;" \
        :: "r"((uint32_t)(smem_result_addr)), "r"((uint32_t)(nCols)) : "memory")
#define TCGEN05_DEALLOC(tmem_addr, nCols) \
    asm volatile("tcgen05.dealloc.cta_group::1.sync.aligned.b32 %0, %1;" \
        :: "r"(tmem_addr), "r"((uint32_t)(nCols)))
#define TCGEN05_RELINQUISH_ALLOC_PERMIT() \
    asm volatile("tcgen05.relinquish_alloc_permit.cta_group::1.sync.aligned;")
#define TCGEN05_COMMIT(mbar_smem_addr) \
    asm volatile("tcgen05.commit.cta_group::1.mbarrier::arrive::one.shared::cluster.b64 [%0];" \
        :: "r"((uint32_t)(mbar_smem_addr)) : "memory")
#define TCGEN05_FENCE_AFTER() \
    asm volatile("tcgen05.fence::after_thread_sync;" ::: "memory")
#define TCGEN05_WAIT_LD() \
    asm volatile("tcgen05.wait::ld.sync.aligned;" ::: "memory")
#define FENCE_PROXY_ASYNC_SHARED_CTA() \
    asm volatile("fence.proxy.async.shared::cta;" ::: "memory")
#define MBARRIER_INIT(mbar_smem_addr, count) \
    asm volatile("mbarrier.init.shared.b64 [%0], %1;" \
        :: "r"((uint32_t)(mbar_smem_addr)), "r"((uint32_t)(count)) : "memory")

#define MBARRIER_WAIT_PARITY(mbar_smem_addr, phase_parity) do { \
    uint32_t _mbar = (uint32_t)(mbar_smem_addr); \
    uint32_t _parity = (uint32_t)(phase_parity); \
    uint32_t _done; \
    asm volatile( \
        "{\n\t.reg .pred p;\n\t" \
        "mbarrier.try_wait.parity.acquire.cta.shared::cta.b64 p, [%1], %2;\n\t" \
        "selp.b32 %0, 1, 0, p;\n\t}" \
        : "=r"(_done) : "r"(_mbar), "r"(_parity) : "memory"); \
    if (!_done) { \
        asm volatile( \
            "{\n\t.reg .pred P1;\n\t" \
            "WAIT_LOOP_%=:\n\t" \
            "mbarrier.try_wait.parity.acquire.cta.shared::cta.b64 P1, [%0], %1, 0x989680;\n\t" \
            "@P1 bra.uni WAIT_DONE_%=;\n\t" \
            "bra.uni WAIT_LOOP_%=;\n\t" \
            "WAIT_DONE_%=:\n\t}" \
            :: "r"(_mbar), "r"(_parity) : "memory"); \
    } \
} while(0)

#define TCGEN05_LD_32X32B_X32(r, tmem_addr) \
    asm volatile( \
        "tcgen05.ld.sync.aligned.32x32b.x32.b32 " \
        "{%0, %1, %2, %3, %4, %5, %6, %7, " \
        " %8, %9, %10, %11, %12, %13, %14, %15, " \
        " %16, %17, %18, %19, %20, %21, %22, %23, " \
        " %24, %25, %26, %27, %28, %29, %30, %31}, [%32];" \
        : "=r"((r)[0]),  "=r"((r)[1]),  "=r"((r)[2]),  "=r"((r)[3]), \
          "=r"((r)[4]),  "=r"((r)[5]),  "=r"((r)[6]),  "=r"((r)[7]), \
          "=r"((r)[8]),  "=r"((r)[9]),  "=r"((r)[10]), "=r"((r)[11]), \
          "=r"((r)[12]), "=r"((r)[13]), "=r"((r)[14]), "=r"((r)[15]), \
          "=r"((r)[16]), "=r"((r)[17]), "=r"((r)[18]), "=r"((r)[19]), \
          "=r"((r)[20]), "=r"((r)[21]), "=r"((r)[22]), "=r"((r)[23]), \
          "=r"((r)[24]), "=r"((r)[25]), "=r"((r)[26]), "=r"((r)[27]), \
          "=r"((r)[28]), "=r"((r)[29]), "=r"((r)[30]), "=r"((r)[31]) \
        : "r"(tmem_addr))

static constexpr unsigned long long SMEM_DESC_BASE_SW128 =
    (2ull << 61) | (1ull << 46) | (64ull << 32) | (1ull << 16);
#define MAKE_SMEM_DESC(a) (SMEM_DESC_BASE_SW128 | ((unsigned long long)((a) >> 4) & 0x3FFF))

__device__ __forceinline__ void mma_bf16_ss(uint32_t d, u64 ad, u64 bd,
                                            uint32_t idesc, uint32_t en) {
    asm volatile(
        "{\n\t.reg .pred p;\n\t"
        "setp.ne.u32 p, %4, 0;\n\t"
        "tcgen05.mma.cta_group::1.kind::f16 [%0], %1, %2, %3, {%5, %5, %5, %5}, p;\n\t"
        "}"
        :: "r"(d), "l"(ad), "l"(bd), "r"(idesc), "r"(en), "r"(0u)
        : "memory");
}

static constexpr uint32_t GEMM_IDESC =
    (1u << 4) | (1u << 7) | (1u << 10) | ((128u / 8) << 17) | ((128u / 16) << 24);
static constexpr uint32_t IDESC_N256 =
    (1u << 4) | (1u << 7) | (1u << 10) | ((256u / 8) << 17) | ((128u / 16) << 24);
#endif // HAS_TCGEN05

// ---------------------------------------------------------------------------
__global__ __launch_bounds__(256) void k_init(const float* __restrict__ x,
                                              const float* __restrict__ Wc,
                                              const float* __restrict__ bc) {
    int idx = blockIdx.x * 256 + threadIdx.x;
    int c  = idx & (NC - 1);
    int bt = idx >> 7;
    float v = x[bt] * Wc[c] + bc[c];
    g_h[idx]    = v;
    g_skip[idx] = 0.f;
    __nv_bfloat16 h = __float2bfloat16(v);
    g_hHi[idx] = h;
    g_hLo[idx] = __float2bfloat16(v - __bfloat162float(h));
}

// ---------------------------------------------------------------------------
__global__ void k_cvtWg(const float* __restrict__ Wt, const float* __restrict__ Ws) {
    int lt = blockIdx.z >> 1, gate = blockIdx.z & 1;
    const float* src = (gate ? Ws : Wt) + (size_t)lt * 128 * 128;
    __shared__ float t[32][33];
    int co0 = blockIdx.x * 32, ci0 = blockIdx.y * 32;
    int tx = threadIdx.x, ty = threadIdx.y;
    #pragma unroll
    for (int r = 0; r < 4; r++)
        t[ty + r*8][tx] = src[(ci0 + ty + r*8) * 128 + co0 + tx];
    __syncthreads();
    #pragma unroll
    for (int r = 0; r < 4; r++) {
        float v = t[tx][ty + r*8];
        int n = gate * 128 + co0 + ty + r*8;
        size_t o = ((size_t)lt * 256 + n) * 128 + ci0 + tx;
        __nv_bfloat16 h = __float2bfloat16(v);
        g_WgHi[o] = h;
        g_WgLo[o] = __float2bfloat16(v - __bfloat162float(h));
    }
}

__global__ void k_cvtWp(const float* __restrict__ Wskip, const float* __restrict__ Wres) {
    int l = blockIdx.z >> 1, gate = blockIdx.z & 1;
    const float* src = (gate ? Wres : Wskip) + (size_t)l * 128 * 128;
    __shared__ float t[32][33];
    int co0 = blockIdx.x * 32, ci0 = blockIdx.y * 32;
    int tx = threadIdx.x, ty = threadIdx.y;
    #pragma unroll
    for (int r = 0; r < 4; r++)
        t[ty + r*8][tx] = src[(ci0 + ty + r*8) * 128 + co0 + tx];
    __syncthreads();
    #pragma unroll
    for (int r = 0; r < 4; r++) {
        float v = t[tx][ty + r*8];
        int n = gate * 128 + co0 + ty + r*8;
        size_t o = ((size_t)l * 256 + n) * 128 + ci0 + tx;
        __nv_bfloat16 h = __float2bfloat16(v);
        g_WpHi[o] = h;
        g_WpLo[o] = __float2bfloat16(v - __bfloat162float(h));
    }
}

// ---------------------------------------------------------------------------
__global__ __launch_bounds__(256) void k_condpre(
    const float* __restrict__ cond,
    const float* __restrict__ Dt, const float* __restrict__ Ds,
    const float* __restrict__ Bt, const float* __restrict__ Bs,
    const float* __restrict__ bt, const float* __restrict__ bs)
{
    int l = blockIdx.y;
    int t2 = blockIdx.x * 2;
    int cop = threadIdx.x;
    int gate = cop >> 7, co = cop & 127;
    __shared__ float sc[NB][NCOND];
    if (cop < NB * NCOND) sc[cop >> 4][cop & 15] = cond[cop];
    __syncthreads();

    const float* D  = gate ? Ds : Dt;
    const float* Bm = gate ? Bs : Bt;
    float bias = (gate ? bs : bt)[l * 128 + co];

    float acc[2][NB];
    #pragma unroll
    for (int tt = 0; tt < 2; tt++)
        #pragma unroll
        for (int b = 0; b < NB; b++) acc[tt][b] = 0.f;

    #pragma unroll 4
    for (int c = 0; c < NCOND; c++) {
        size_t base = (((size_t)l * NCOND + c) * TT + t2) * 128 + co;
        float d0 = D[base], d1 = D[base + 128];
        #pragma unroll
        for (int b = 0; b < NB; b++) {
            acc[0][b] = fmaf(sc[b][c], d0, acc[0][b]);
            acc[1][b] = fmaf(sc[b][c], d1, acc[1][b]);
        }
    }
    #pragma unroll
    for (int tt = 0; tt < 2; tt++) {
        float bm = Bm[((size_t)l * TT + t2 + tt) * 128 + co] + bias;
        #pragma unroll
        for (int b = 0; b < NB; b++)
            g_tcond[(((size_t)l * NB + b) * TT + t2 + tt) * 256 + cop] = acc[tt][b] + bm;
    }
}

// ---------------------------------------------------------------------------
// Fused residual layer. smem: 2048 hdr + 198656 G region.
//   gate bufs: G+0/98304 (each: Ah16K Al16K Bh32K Bl32K)
//   tcond stage: G+65536, [t 128][260 f] (after gate drain)
//   g A-tiles: G+0..64K ; post W: G+65536..192K ; ep2 stage: G+0, [row][260 f]
// ---------------------------------------------------------------------------
#define LAYER_SMEM 200704

__global__ __launch_bounds__(256, 1) void k_layer(
    int l, int d, const float* __restrict__ bskip, const float* __restrict__ bres)
{
#if HAS_TCGEN05
    extern __shared__ char dsm[];
    const int tid = threadIdx.x;
    const int wid = tid >> 5;
    const int lane = tid & 31;

    uint32_t raw = smem_to_u32(dsm);
    uint32_t abase = (raw + 1023) & ~1023u;
    char* hdr = dsm + (abase - raw);
    char* G   = hdr + 2048;
    const uint32_t hdr_a = abase;
    const uint32_t G_a   = abase + 2048;

    const int b  = blockIdx.x >> 4;
    const int t0 = (blockIdx.x & 15) << 7;

    if (tid == 0) {
        MBARRIER_INIT(hdr_a + 8, 1);
        MBARRIER_INIT(hdr_a + 16, 1);
    }
    if (wid == 0) TCGEN05_ALLOC(hdr_a, 512);
    __syncthreads();

    uint32_t tmem;
    asm volatile("ld.shared.b32 %0, [%1];" : "=r"(tmem) : "r"(hdr_a));

    int phase[2] = {0, 0};

    // ---- gate phase: 6 chunks, register-prefetched loads ----
    for (int ch = 0; ch < 6; ch++) {
        const int buf = ch & 1;
        char* Gb = G + buf * 98304;
        const uint32_t Gb_a = G_a + buf * 98304;
        const int tap = ch >> 1;
        const int ci0 = (ch & 1) << 6;

        // prefetch LDGs into registers (no smem dependency)
        uint4 va[8];
        const int r2 = tid >> 1, half = tid & 1;
        {
            int trow = t0 + r2 + (tap - 1) * d;
            bool ok = (unsigned)trow < (unsigned)TT;
            size_t goff = ((size_t)(b * TT + (ok ? trow : 0))) * NC + ci0 + half * 32;
            #pragma unroll
            for (int q = 0; q < 4; q++) {
                if (ok) {
                    va[q]     = *(const uint4*)(g_hHi + goff + q * 8);
                    va[4 + q] = *(const uint4*)(g_hLo + goff + q * 8);
                } else {
                    va[q] = make_uint4(0,0,0,0);
                    va[4 + q] = make_uint4(0,0,0,0);
                }
            }
        }
        uint4 wb[16];
        {
            size_t woff = (((size_t)(l * 3 + tap)) * 256 + tid) * 128 + ci0;
            #pragma unroll
            for (int q = 0; q < 8; q++) {
                wb[q]     = *(const uint4*)(g_WgHi + woff + q * 8);
                wb[8 + q] = *(const uint4*)(g_WgLo + woff + q * 8);
            }
        }

        if (ch >= 2) {
            MBARRIER_WAIT_PARITY(hdr_a + 8 + 8 * buf, phase[buf]);
            phase[buf] ^= 1;
        }

        #pragma unroll
        for (int q = 0; q < 4; q++) {
            int c = half * 4 + q;
            uint32_t so = r2 * 128 + (((uint32_t)(c ^ (r2 & 7))) << 4);
            *(uint4*)(Gb + so)         = va[q];
            *(uint4*)(Gb + 16384 + so) = va[4 + q];
        }
        #pragma unroll
        for (int q = 0; q < 8; q++) {
            uint32_t so = tid * 128 + (((uint32_t)(q ^ (tid & 7))) << 4);
            *(uint4*)(Gb + 32768 + so) = wb[q];
            *(uint4*)(Gb + 65536 + so) = wb[8 + q];
        }
        FENCE_PROXY_ASYNC_SHARED_CTA();
        __syncthreads();

        if (wid == 0 && elect_one_pred()) {
            u64 dAh = MAKE_SMEM_DESC(Gb_a);
            u64 dAl = MAKE_SMEM_DESC(Gb_a + 16384);
            u64 dBh = MAKE_SMEM_DESC(Gb_a + 32768);
            u64 dBl = MAKE_SMEM_DESC(Gb_a + 65536);
            uint32_t en = (ch != 0);
            #pragma unroll
            for (int ks = 0; ks < 4; ks++) {
                mma_bf16_ss(tmem, dAh + 2*ks, dBh + 2*ks, IDESC_N256, en); en = 1;
                mma_bf16_ss(tmem, dAh + 2*ks, dBl + 2*ks, IDESC_N256, 1);
                mma_bf16_ss(tmem, dAl + 2*ks, dBh + 2*ks, IDESC_N256, 1);
            }
            TCGEN05_COMMIT(hdr_a + 8 + 8 * buf);
        }
    }

    MBARRIER_WAIT_PARITY(hdr_a + 8,  phase[0]);
    MBARRIER_WAIT_PARITY(hdr_a + 16, phase[1]);
    const int postPh = phase[0] ^ 1;
    TCGEN05_FENCE_AFTER();
    __syncthreads();

    // ---- stage tcond coalesced into smem [t 128][260 f] ----
    float* tcS = (float*)(G + 65536);
    {
        const float* tcg = g_tcond + (((size_t)l * NB + b) * TT + t0) * 256;
        #pragma unroll
        for (int k = 0; k < 32; k++) {
            int i4 = tid + k * 256;            // 8192 float4
            int row = i4 >> 6, c4 = (i4 & 63) << 2;
            float4 v = *(const float4*)(tcg + (size_t)row * 256 + c4);
            *(float4*)(tcS + row * 260 + c4) = v;
        }
    }
    __syncthreads();

    // ---- epilogue 1 (8 warps): g = tanh * sigmoid -> bf16 A-tiles ----
    {
        const int row = (wid & 3) * 32 + lane;
        const int cho = (wid >> 2) * 64;
        const float* trow_ = tcS + row * 260;
        #pragma unroll 1
        for (int half2 = 0; half2 < 2; half2++) {
            int c0 = cho + half2 * 32;
            uint32_t rt[32], rs[32];
            TCGEN05_LD_32X32B_X32(rt, tmem + c0);
            TCGEN05_LD_32X32B_X32(rs, tmem + 128 + c0);
            TCGEN05_WAIT_LD();
            #pragma unroll
            for (int j = 0; j < 32; j += 4) {
                int c = c0 + j;
                float4 ta = *(const float4*)(trow_ + c);
                float4 tx = *(const float4*)(trow_ + 128 + c);
                float av[4] = {__uint_as_float(rt[j])   + ta.x,
                               __uint_as_float(rt[j+1]) + ta.y,
                               __uint_as_float(rt[j+2]) + ta.z,
                               __uint_as_float(rt[j+3]) + ta.w};
                float xv[4] = {__uint_as_float(rs[j])   + tx.x,
                               __uint_as_float(rs[j+1]) + tx.y,
                               __uint_as_float(rs[j+2]) + tx.z,
                               __uint_as_float(rs[j+3]) + tx.w};
                __nv_bfloat16 hv[4], lv[4];
                #pragma unroll
                for (int q = 0; q < 4; q++) {
                    float gv = tanh_fast(av[q]) * sig_fast(xv[q]);
                    hv[q] = __float2bfloat16(gv);
                    lv[q] = __float2bfloat16(gv - __bfloat162float(hv[q]));
                }
                uint32_t off = row * 128 + (c & 63) * 2;
                off ^= (off >> 3) & 0x70;
                char* atp = G + ((c >> 6) * 32768);
                *(uint2*)(atp + off)         = *(const uint2*)hv;
                *(uint2*)(atp + 16384 + off) = *(const uint2*)lv;
            }
        }
    }
    __syncthreads();

    // ---- post weights into G+65536..196608 ----
    {
        size_t woff = ((size_t)l * 256 + tid) * 128;
        #pragma unroll
        for (int cc = 0; cc < 2; cc++) {
            char* dst = G + 65536 + cc * 65536;
            #pragma unroll
            for (int q = 0; q < 8; q++) {
                uint32_t so = tid * 128 + (((uint32_t)(q ^ (tid & 7))) << 4);
                *(uint4*)(dst + so)         = *(const uint4*)(g_WpHi + woff + cc*64 + q*8);
                *(uint4*)(dst + 32768 + so) = *(const uint4*)(g_WpLo + woff + cc*64 + q*8);
            }
        }
    }
    FENCE_PROXY_ASYNC_SHARED_CTA();
    __syncthreads();

    // ---- post MMA ----
    if (wid == 0 && elect_one_pred()) {
        uint32_t en = 0;
        #pragma unroll
        for (int cc = 0; cc < 2; cc++) {
            u64 dAh = MAKE_SMEM_DESC(G_a + cc * 32768);
            u64 dAl = MAKE_SMEM_DESC(G_a + cc * 32768 + 16384);
            u64 dBh = MAKE_SMEM_DESC(G_a + 65536 + cc * 65536);
            u64 dBl = MAKE_SMEM_DESC(G_a + 65536 + cc * 65536 + 32768);
            #pragma unroll
            for (int ks = 0; ks < 4; ks++) {
                mma_bf16_ss(tmem + 256, dAh + 2*ks, dBh + 2*ks, IDESC_N256, en); en = 1;
                mma_bf16_ss(tmem + 256, dAh + 2*ks, dBl + 2*ks, IDESC_N256, 1);
                mma_bf16_ss(tmem + 256, dAl + 2*ks, dBh + 2*ks, IDESC_N256, 1);
            }
        }
        TCGEN05_COMMIT(hdr_a + 8);
    }
    MBARRIER_WAIT_PARITY(hdr_a + 8, postPh);
    TCGEN05_FENCE_AFTER();
    __syncthreads();

    // ---- epilogue 2a (8 warps): stage D2 into smem [row][260 f] ----
    float* st = (float*)G;
    {
        const int row = (wid & 3) * 32 + lane;
        const int g2 = wid >> 2;
        #pragma unroll 1
        for (int bt2 = 0; bt2 < 2; bt2++) {
            int c0 = g2 * 128 + bt2 * 64;
            uint32_t ra[32], rb[32];
            TCGEN05_LD_32X32B_X32(ra, tmem + 256 + c0);
            TCGEN05_LD_32X32B_X32(rb, tmem + 256 + c0 + 32);
            TCGEN05_WAIT_LD();
            #pragma unroll
            for (int j = 0; j < 32; j += 4) {
                float4 v1 = make_float4(__uint_as_float(ra[j]),   __uint_as_float(ra[j+1]),
                                        __uint_as_float(ra[j+2]), __uint_as_float(ra[j+3]));
                float4 v2 = make_float4(__uint_as_float(rb[j]),   __uint_as_float(rb[j+1]),
                                        __uint_as_float(rb[j+2]), __uint_as_float(rb[j+3]));
                *(float4*)(st + row * 260 + c0 + j)      = v1;
                *(float4*)(st + row * 260 + c0 + 32 + j) = v2;
            }
        }
    }
    __syncthreads();

    // ---- epilogue 2b: coalesced RMW of skip/h + refresh h split ----
    {
        const size_t gbase = ((size_t)(b * TT + t0)) * NC;
        #pragma unroll
        for (int k = 0; k < 16; k++) {
            int e = tid + k * 256;             // 4096 float4
            int row = e >> 5, c4 = (e & 31) << 2;
            float4 dsk = *(const float4*)(st + row * 260 + c4);
            float4 dre = *(const float4*)(st + row * 260 + 128 + c4);
            float4 bk4 = *(const float4*)(bskip + l * 128 + c4);
            float4 br4 = *(const float4*)(bres  + l * 128 + c4);
            size_t go = gbase + (size_t)row * NC + c4;
            float4 sk = *(const float4*)(g_skip + go);
            float4 hh = *(const float4*)(g_h + go);
            sk.x += dsk.x + bk4.x; sk.y += dsk.y + bk4.y;
            sk.z += dsk.z + bk4.z; sk.w += dsk.w + bk4.w;
            hh.x += dre.x + br4.x; hh.y += dre.y + br4.y;
            hh.z += dre.z + br4.z; hh.w += dre.w + br4.w;
            *(float4*)(g_skip + go) = sk;
            *(float4*)(g_h + go) = hh;
            float hq[4] = {hh.x, hh.y, hh.z, hh.w};
            __nv_bfloat16 hv[4], lv[4];
            #pragma unroll
            for (int q = 0; q < 4; q++) {
                hv[q] = __float2bfloat16(hq[q]);
                lv[q] = __float2bfloat16(hq[q] - __bfloat162float(hv[q]));
            }
            *(uint2*)(g_hHi + go) = *(const uint2*)hv;
            *(uint2*)(g_hLo + go) = *(const uint2*)lv;
        }
    }
    __syncthreads();
    if (wid == 0) {
        TCGEN05_RELINQUISH_ALLOC_PERMIT();
        TCGEN05_DEALLOC(tmem, 512);
    }
#endif // HAS_TCGEN05
}

// ---------------------------------------------------------------------------
__global__ __launch_bounds__(256) void k_cvtA() {
    int i = (blockIdx.x * 256 + threadIdx.x) * 4;
    float4 v = *(const float4*)(g_skip + i);
    __nv_bfloat16 h[4], l[4];
    float vv[4] = {v.x, v.y, v.z, v.w};
    #pragma unroll
    for (int j = 0; j < 4; j++) {
        h[j] = __float2bfloat16(vv[j]);
        l[j] = __float2bfloat16(vv[j] - __bfloat162float(h[j]));
    }
    *(uint2*)(g_skipHi + i) = *(const uint2*)h;
    *(uint2*)(g_skipLo + i) = *(const uint2*)l;
}

// ---------------------------------------------------------------------------
__global__ void k_cvtW(const float* __restrict__ src,
                       __nv_bfloat16* __restrict__ dhi,
                       __nv_bfloat16* __restrict__ dlo, int K, int N) {
    __shared__ float t[32][33];
    int tap = blockIdx.z;
    int n0 = blockIdx.x * 32, k0 = blockIdx.y * 32;
    int tx = threadIdx.x, ty = threadIdx.y;
    #pragma unroll
    for (int r = 0; r < 4; r++)
        t[ty + r*8][tx] = src[((size_t)tap*K + k0 + ty + r*8) * N + n0 + tx];
    __syncthreads();
    #pragma unroll
    for (int r = 0; r < 4; r++) {
        float v = t[tx][ty + r*8];
        __nv_bfloat16 h = __float2bfloat16(v);
        __nv_bfloat16 l = __float2bfloat16(v - __bfloat162float(h));
        size_t o = ((size_t)tap*N + n0 + ty + r*8) * K + k0 + tx;
        dhi[o] = h; dlo[o] = l;
    }
}

// ---------------------------------------------------------------------------
// Head GEMM-conv3 with register-prefetched loads + staged coalesced epilogue
// ---------------------------------------------------------------------------
#define GEMM_SMEM (1024 + 1024 + 131072)

template<bool WB16>
__global__ __launch_bounds__(256, 1) void k_gemm(
    const __nv_bfloat16* __restrict__ aHi, const __nv_bfloat16* __restrict__ aLo,
    const __nv_bfloat16* __restrict__ wHi, const __nv_bfloat16* __restrict__ wLo,
    const float* __restrict__ bias,
    __nv_bfloat16* __restrict__ oHi, __nv_bfloat16* __restrict__ oLo,
    float* __restrict__ oF, int Cin, int CO)
{
#if HAS_TCGEN05
    extern __shared__ char dsm[];
    const int tid = threadIdx.x;
    const int wid = tid >> 5;
    const int lane = tid & 31;

    uint32_t raw = smem_to_u32(dsm);
    uint32_t abase = (raw + 1023) & ~1023u;
    char* hdr   = dsm + (abase - raw);
    char* tiles = hdr + 1024;
    const uint32_t hdr_a   = abase;
    const uint32_t tiles_a = abase + 1024;
    float* sbias = (float*)(hdr + 512);

    const int b  = blockIdx.x >> 4;
    const int t0 = (blockIdx.x & 15) * 128;
    const int n0 = blockIdx.y * 128;

    if (tid == 0) {
        MBARRIER_INIT(hdr_a + 8, 1);
        MBARRIER_INIT(hdr_a + 16, 1);
    }
    if (wid == 0) TCGEN05_ALLOC(hdr_a, 128);
    if (tid < 128) sbias[tid] = bias[n0 + tid];
    __syncthreads();

    uint32_t tmem;
    asm volatile("ld.shared.b32 %0, [%1];" : "=r"(tmem) : "r"(hdr_a));

    const int nci = Cin >> 6;
    const int nchunks = 3 * nci;
    const size_t aBatch = (size_t)b * TT * Cin;

    int phase[2] = {0, 0};

    for (int ch = 0; ch < nchunks; ch++) {
        const int buf = ch & 1;
        char* tb = tiles + buf * 65536;
        const uint32_t tb_a = tiles_a + buf * 65536;

        const int tap = ch / nci;
        const int ci0 = (ch - tap * nci) << 6;
        const size_t bBase = ((size_t)tap * CO + n0) * Cin + ci0;
        const int c = tid & 7;

        // register prefetch
        uint4 va[8], vb[8];
        #pragma unroll
        for (int p = 0; p < 4; p++) {
            int r = p * 32 + (tid >> 3);
            int trow = t0 + r + tap - 1;
            if ((unsigned)trow < (unsigned)TT) {
                size_t off = aBatch + (size_t)trow * Cin + ci0 + c * 8;
                va[p]     = *(const uint4*)(aHi + off);
                va[4 + p] = *(const uint4*)(aLo + off);
            } else {
                va[p] = make_uint4(0,0,0,0);
                va[4 + p] = make_uint4(0,0,0,0);
            }
            size_t bo = bBase + (size_t)r * Cin + c * 8;
            vb[p]     = *(const uint4*)(wHi + bo);
            vb[4 + p] = *(const uint4*)(wLo + bo);
        }

        if (ch >= 2) {
            MBARRIER_WAIT_PARITY(hdr_a + 8 + 8 * buf, phase[buf]);
            phase[buf] ^= 1;
        }

        #pragma unroll
        for (int p = 0; p < 4; p++) {
            int r = p * 32 + (tid >> 3);
            uint32_t so = r * 128 + (((uint32_t)(c ^ (r & 7))) << 4);
            *(uint4*)(tb + so)         = va[p];
            *(uint4*)(tb + 16384 + so) = va[4 + p];
            *(uint4*)(tb + 32768 + so) = vb[p];
            *(uint4*)(tb + 49152 + so) = vb[4 + p];
        }
        FENCE_PROXY_ASYNC_SHARED_CTA();
        __syncthreads();

        if (wid == 0 && elect_one_pred()) {
            u64 dAh = MAKE_SMEM_DESC(tb_a);
            u64 dAl = MAKE_SMEM_DESC(tb_a + 16384);
            u64 dBh = MAKE_SMEM_DESC(tb_a + 32768);
            u64 dBl = MAKE_SMEM_DESC(tb_a + 49152);
            uint32_t en = (ch != 0);
            #pragma unroll
            for (int ks = 0; ks < 4; ks++) {
                mma_bf16_ss(tmem, dAh + 2*ks, dBh + 2*ks, GEMM_IDESC, en); en = 1;
                mma_bf16_ss(tmem, dAh + 2*ks, dBl + 2*ks, GEMM_IDESC, 1);
                mma_bf16_ss(tmem, dAl + 2*ks, dBh + 2*ks, GEMM_IDESC, 1);
            }
            TCGEN05_COMMIT(hdr_a + 8 + 8 * buf);
        }
    }

    MBARRIER_WAIT_PARITY(hdr_a + 8,  phase[0]);
    MBARRIER_WAIT_PARITY(hdr_a + 16, phase[1]);
    TCGEN05_FENCE_AFTER();
    __syncthreads();

    // ---- staged epilogue ----
    if (WB16) {
        // stage hi/lo bf16 [row][136] (272B row stride)
        char* hiS = tiles;
        char* loS = tiles + 34816;
        {
            const int m = (wid & 3) * 32 + lane;
            const int cg = (wid >> 2) * 64;
            #pragma unroll 1
            for (int half2 = 0; half2 < 2; half2++) {
                int c0 = cg + half2 * 32;
                uint32_t r32[32];
                TCGEN05_LD_32X32B_X32(r32, tmem + c0);
                TCGEN05_WAIT_LD();
                #pragma unroll
                for (int j = 0; j < 32; j += 2) {
                    __nv_bfloat16 hv[2], lv[2];
                    #pragma unroll
                    for (int q = 0; q < 2; q++) {
                        float v = __uint_as_float(r32[j+q]) + sbias[c0 + j + q];
                        v = fmaxf(v, 0.f);
                        hv[q] = __float2bfloat16(v);
                        lv[q] = __float2bfloat16(v - __bfloat162float(hv[q]));
                    }
                    uint32_t so = m * 272 + (c0 + j) * 2;
                    *(uint32_t*)(hiS + so) = *(const uint32_t*)hv;
                    *(uint32_t*)(loS + so) = *(const uint32_t*)lv;
                }
            }
        }
        __syncthreads();
        #pragma unroll
        for (int k = 0; k < 8; k++) {
            int e = tid + k * 256;             // 2048 uint4 (8 bf16 each)
            int row = e >> 4, cu = e & 15;
            uint4 h4 = *(const uint4*)(hiS + row * 272 + cu * 16);
            uint4 l4 = *(const uint4*)(loS + row * 272 + cu * 16);
            size_t o = (size_t)(b * TT + t0 + row) * CO + n0 + cu * 8;
            *(uint4*)(oHi + o) = h4;
            *(uint4*)(oLo + o) = l4;
        }
    } else {
        float* fS = (float*)tiles;             // [row][132 f]
        {
            const int m = (wid & 3) * 32 + lane;
            const int cg = (wid >> 2) * 64;
            #pragma unroll 1
            for (int half2 = 0; half2 < 2; half2++) {
                int c0 = cg + half2 * 32;
                uint32_t r32[32];
                TCGEN05_LD_32X32B_X32(r32, tmem + c0);
                TCGEN05_WAIT_LD();
                #pragma unroll
                for (int j = 0; j < 32; j += 4) {
                    float4 v;
                    v.x = fmaxf(__uint_as_float(r32[j])   + sbias[c0+j],   0.f);
                    v.y = fmaxf(__uint_as_float(r32[j+1]) + sbias[c0+j+1], 0.f);
                    v.z = fmaxf(__uint_as_float(r32[j+2]) + sbias[c0+j+2], 0.f);
                    v.w = fmaxf(__uint_as_float(r32[j+3]) + sbias[c0+j+3], 0.f);
                    *(float4*)(fS + m * 132 + c0 + j) = v;
                }
            }
        }
        __syncthreads();
        #pragma unroll
        for (int k = 0; k < 16; k++) {
            int e = tid + k * 256;             // 4096 float4
            int row = e >> 5, c4 = (e & 31) << 2;
            float4 v = *(const float4*)(fS + row * 132 + c4);
            *(float4*)(oF + (size_t)(b * TT + t0 + row) * CO + n0 + c4) = v;
        }
    }

    __syncthreads();
    if (wid == 0) {
        TCGEN05_RELINQUISH_ALLOC_PERMIT();
        TCGEN05_DEALLOC(tmem, 128);
    }
#endif // HAS_TCGEN05
}

// ---------------------------------------------------------------------------
__global__ __launch_bounds__(128) void k_head3(const float* __restrict__ W3,
                                               const float* __restrict__ b3,
                                               float* __restrict__ out)
{
    int row  = blockIdx.x * 4 + (threadIdx.x >> 5);
    int lane = threadIdx.x & 31;
    const float* p = g_out2 + (size_t)row * 256;
    float s = 0.f;
    #pragma unroll
    for (int i = 0; i < 8; i++) s = fmaf(p[lane + 32 * i], W3[lane + 32 * i], s);
    #pragma unroll
    for (int o = 16; o; o >>= 1) s += __shfl_xor_sync(0xffffffffu, s, o);
    if (lane == 0) out[row] = tanhf(s + b3[0]);
}

// ---------------------------------------------------------------------------
extern "C" void kernel_launch(void* const* d_in, const int* in_sizes, int n_in,
                              void* d_out, int out_size) {
    const float* x     = (const float*)d_in[0];
    const float* cond  = (const float*)d_in[1];
    const float* Wc    = (const float*)d_in[2];
    const float* bc    = (const float*)d_in[3];
    const float* Wt    = (const float*)d_in[4];
    const float* bt    = (const float*)d_in[5];
    const float* Ws    = (const float*)d_in[6];
    const float* bs    = (const float*)d_in[7];
    const float* Dt    = (const float*)d_in[8];
    const float* Bt    = (const float*)d_in[9];
    const float* Ds    = (const float*)d_in[10];
    const float* Bs    = (const float*)d_in[11];
    const float* Wskip = (const float*)d_in[12];
    const float* bskip = (const float*)d_in[13];
    const float* Wres  = (const float*)d_in[14];
    const float* bres  = (const float*)d_in[15];
    const float* W1    = (const float*)d_in[16];
    const float* b1    = (const float*)d_in[17];
    const float* W2    = (const float*)d_in[18];
    const float* b2    = (const float*)d_in[19];
    const float* W3    = (const float*)d_in[20];
    const float* b3    = (const float*)d_in[21];
    float* out = (float*)d_out;

    cudaFuncSetAttribute(k_gemm<true>,  cudaFuncAttributeMaxDynamicSharedMemorySize, GEMM_SMEM);
    cudaFuncSetAttribute(k_gemm<false>, cudaFuncAttributeMaxDynamicSharedMemorySize, GEMM_SMEM);
    cudaFuncSetAttribute(k_layer, cudaFuncAttributeMaxDynamicSharedMemorySize, LAYER_SMEM);

    __nv_bfloat16 *skipHi, *skipLo, *w1h, *w1l, *w2h, *w2l, *o1h, *o1l;
    float* out2p;
    cudaGetSymbolAddress((void**)&skipHi, g_skipHi);
    cudaGetSymbolAddress((void**)&skipLo, g_skipLo);
    cudaGetSymbolAddress((void**)&w1h, g_W1tHi);
    cudaGetSymbolAddress((void**)&w1l, g_W1tLo);
    cudaGetSymbolAddress((void**)&w2h, g_W2tHi);
    cudaGetSymbolAddress((void**)&w2l, g_W2tLo);
    cudaGetSymbolAddress((void**)&o1h, g_out1Hi);
    cudaGetSymbolAddress((void**)&o1l, g_out1Lo);
    cudaGetSymbolAddress((void**)&out2p, g_out2);

    k_cvtWg<<<dim3(4, 4, NL * 3 * 2), dim3(32, 8)>>>(Wt, Ws);
    k_cvtWp<<<dim3(4, 4, NL * 2),     dim3(32, 8)>>>(Wskip, Wres);
    k_cvtW<<<dim3(2048/32, 128/32, 3),  dim3(32, 8)>>>(W1, w1h, w1l, 128, 2048);
    k_cvtW<<<dim3(256/32, 2048/32, 3),  dim3(32, 8)>>>(W2, w2h, w2l, 2048, 256);
    k_condpre<<<dim3(TT/2, NL), 256>>>(cond, Dt, Ds, Bt, Bs, bt, bs);

    k_init<<<NB * TT * NC / 256, 256>>>(x, Wc, bc);

    const int dil[NL] = {1, 2, 4, 8, 16, 32, 64, 128, 256, 512};
    for (int l = 0; l < NL; l++)
        k_layer<<<NB * (TT/128), 256, LAYER_SMEM>>>(l, dil[l], bskip, bres);

    k_cvtA<<<NB * TT * NC / 1024, 256>>>();

    k_gemm<true><<<dim3(128, 16), 256, GEMM_SMEM>>>(
        skipHi, skipLo, w1h, w1l, b1, o1h, o1l, nullptr, 128, 2048);
    k_gemm<false><<<dim3(128, 2), 256, GEMM_SMEM>>>(
        o1h, o1l, w2h, w2l, b2, nullptr, nullptr, out2p, 2048, 256);

    k_head3<<<NB * TT / 4, 128>>>(W3, b3, out);
}